// round 12
// baseline (speedup 1.0000x reference)
#include <cuda_runtime.h>
#include <cstdint>

#define S_LEN   1560
#define DIMN    1536
#define NHN     12
#define HDN     128
#define LKV     10920
#define CSTART  9360
#define QK_SCALE 0.08838834764831845f

typedef unsigned long long u64;

// ---------------- scratch (device globals; no allocations) ----------------
__device__ float g_q[S_LEN * DIMN];
__device__ float g_k[S_LEN * DIMN];
__device__ float g_v[S_LEN * DIMN];
__device__ float g_o[S_LEN * DIMN];

// ---------------- packed f32x2 helpers ----------------
__device__ __forceinline__ u64 f2fma(u64 a, u64 b, u64 c) {
    u64 d;
    asm("fma.rn.f32x2 %0, %1, %2, %3;" : "=l"(d) : "l"(a), "l"(b), "l"(c));
    return d;
}
__device__ __forceinline__ u64 f2mul(u64 a, u64 b) {
    u64 d;
    asm("mul.rn.f32x2 %0, %1, %2;" : "=l"(d) : "l"(a), "l"(b));
    return d;
}
__device__ __forceinline__ u64 splat2(float x) {
    u64 d; unsigned xi = __float_as_uint(x);
    asm("mov.b64 %0, {%1, %1};" : "=l"(d) : "r"(xi));
    return d;
}
__device__ __forceinline__ float f2lo(u64 v) { return __uint_as_float((unsigned)(v & 0xffffffffull)); }
__device__ __forceinline__ float f2hi(u64 v) { return __uint_as_float((unsigned)(v >> 32)); }

// =======================================================================
// NT GEMM: C[m][n] = sum_k A[m][k]*W[n][k] + bias[n]
// M=1560 (guarded), N=K=1536. 128x128x16 tile, 256 threads, 8x8 microkernel.
// =======================================================================
__device__ __forceinline__ void gemm_body(const float* __restrict__ A,
                                          const float* __restrict__ W,
                                          const float* __restrict__ bias,
                                          float* __restrict__ C)
{
    __shared__ float As[16][128];
    __shared__ float Bs[16][128];

    const int m0 = blockIdx.y * 128;
    const int n0 = blockIdx.x * 128;
    const int tid = threadIdx.x;
    const int ty = tid >> 4, tx = tid & 15;
    const int lr = tid >> 2;            // 0..63
    const int lk = (tid & 3) * 4;       // 0,4,8,12

    float c[8][8];
#pragma unroll
    for (int i = 0; i < 8; i++)
#pragma unroll
        for (int j = 0; j < 8; j++) c[i][j] = 0.f;

    for (int k0 = 0; k0 < DIMN; k0 += 16) {
#pragma unroll
        for (int q = 0; q < 2; q++) {
            int m = m0 + lr + q * 64;
            float4 va = (m < S_LEN) ? *(const float4*)(A + (size_t)m * DIMN + k0 + lk)
                                    : make_float4(0.f, 0.f, 0.f, 0.f);
            As[lk + 0][lr + q * 64] = va.x;
            As[lk + 1][lr + q * 64] = va.y;
            As[lk + 2][lr + q * 64] = va.z;
            As[lk + 3][lr + q * 64] = va.w;
            int n = n0 + lr + q * 64;
            float4 vb = *(const float4*)(W + (size_t)n * DIMN + k0 + lk);
            Bs[lk + 0][lr + q * 64] = vb.x;
            Bs[lk + 1][lr + q * 64] = vb.y;
            Bs[lk + 2][lr + q * 64] = vb.z;
            Bs[lk + 3][lr + q * 64] = vb.w;
        }
        __syncthreads();
#pragma unroll
        for (int kk = 0; kk < 16; kk++) {
            float a[8], b[8];
            *(float4*)&a[0] = *(const float4*)&As[kk][ty * 8];
            *(float4*)&a[4] = *(const float4*)&As[kk][ty * 8 + 4];
            *(float4*)&b[0] = *(const float4*)&Bs[kk][tx * 8];
            *(float4*)&b[4] = *(const float4*)&Bs[kk][tx * 8 + 4];
#pragma unroll
            for (int i = 0; i < 8; i++)
#pragma unroll
                for (int j = 0; j < 8; j++)
                    c[i][j] = fmaf(a[i], b[j], c[i][j]);
        }
        __syncthreads();
    }

    float4 bia = *(const float4*)(bias + n0 + tx * 8);
    float4 bib = *(const float4*)(bias + n0 + tx * 8 + 4);
#pragma unroll
    for (int i = 0; i < 8; i++) {
        int m = m0 + ty * 8 + i;
        if (m >= S_LEN) continue;
        float4 r0 = make_float4(c[i][0] + bia.x, c[i][1] + bia.y,
                                c[i][2] + bia.z, c[i][3] + bia.w);
        float4 r1 = make_float4(c[i][4] + bib.x, c[i][5] + bib.y,
                                c[i][6] + bib.z, c[i][7] + bib.w);
        *(float4*)(C + (size_t)m * DIMN + n0 + tx * 8) = r0;
        *(float4*)(C + (size_t)m * DIMN + n0 + tx * 8 + 4) = r1;
    }
}

__global__ void __launch_bounds__(256) gemm_qkv(
    const float* __restrict__ x,
    const float* __restrict__ wq, const float* __restrict__ bq,
    const float* __restrict__ wk, const float* __restrict__ bk,
    const float* __restrict__ wv, const float* __restrict__ bv)
{
    const float* W; const float* B; float* C;
    if (blockIdx.z == 0)      { W = wq; B = bq; C = g_q; }
    else if (blockIdx.z == 1) { W = wk; B = bk; C = g_k; }
    else                      { W = wv; B = bv; C = g_v; }
    gemm_body(x, W, B, C);
}

__global__ void __launch_bounds__(256) gemm_out(
    const float* __restrict__ wo, const float* __restrict__ bo,
    float* __restrict__ out)
{
    gemm_body(g_o, wo, bo, out);
}

// =======================================================================
// rmsnorm(1536) + 3-band RoPE, one block per token, in-place on g_q/g_k.
// token s: f=0, h=s/52, w=s%52; c<22 -> row 6, c<43 -> row h, else row w.
// =======================================================================
__global__ void __launch_bounds__(256) normrope_kernel(
    const float* __restrict__ gq, const float* __restrict__ gk,
    const float* __restrict__ fcos, const float* __restrict__ fsin)
{
    const int s = blockIdx.x;
    float* qr = g_q + (size_t)s * DIMN;
    float* kr = g_k + (size_t)s * DIMN;
    const int tid = threadIdx.x;

    float sq = 0.f, sk = 0.f;
#pragma unroll
    for (int u = 0; u < 6; u++) {
        float a = qr[tid + u * 256]; sq = fmaf(a, a, sq);
        float b = kr[tid + u * 256]; sk = fmaf(b, b, sk);
    }
#pragma unroll
    for (int off = 16; off; off >>= 1) {
        sq += __shfl_xor_sync(0xffffffffu, sq, off);
        sk += __shfl_xor_sync(0xffffffffu, sk, off);
    }
    __shared__ float red[2][8];
    if ((tid & 31) == 0) { red[0][tid >> 5] = sq; red[1][tid >> 5] = sk; }
    __syncthreads();
    float tq = 0.f, tk = 0.f;
#pragma unroll
    for (int w = 0; w < 8; w++) { tq += red[0][w]; tk += red[1][w]; }
    const float invq = rsqrtf(tq * (1.0f / DIMN) + 1e-6f);
    const float invk = rsqrtf(tk * (1.0f / DIMN) + 1e-6f);

    const int h_tok = s / 52;
    const int w_tok = s - h_tok * 52;

#pragma unroll
    for (int p = tid; p < NHN * 64; p += 256) {
        int hh = p >> 6;
        int c = p & 63;
        int r = (c < 22) ? 6 : ((c < 43) ? h_tok : w_tok);
        float cs = fcos[r * 64 + c];
        float sn = fsin[r * 64 + c];
        int idx = hh * HDN + 2 * c;

        float qe = qr[idx] * invq * gq[idx];
        float qo = qr[idx + 1] * invq * gq[idx + 1];
        qr[idx]     = qe * cs - qo * sn;
        qr[idx + 1] = qe * sn + qo * cs;

        float ke = kr[idx] * invk * gk[idx];
        float ko = kr[idx + 1] * invk * gk[idx + 1];
        kr[idx]     = ke * cs - ko * sn;
        kr[idx + 1] = ke * sn + ko * cs;
    }
}

// =======================================================================
// Flash attention: grid (25 q-tiles, 12 heads), 256 threads, 64x64 tiles.
// Keys/values: pos < 9360 from cache, else from roped g_k / g_v.
// Dyn smem: Qs/Ks/Vs 64x132 + Ps 64x68 = 118784 B.
// =======================================================================
#define ATTN_SMEM ((3 * 64 * 132 + 64 * 68) * 4)

__global__ void __launch_bounds__(256) attn_kernel(
    const float* __restrict__ cache_k, const float* __restrict__ cache_v)
{
    extern __shared__ float sm[];
    float* Qs = sm;                    // 64 x 132
    float* Ks = Qs + 64 * 132;
    float* Vs = Ks + 64 * 132;
    float* Ps = Vs + 64 * 132;         // 64 x 68

    const int h  = blockIdx.y;
    const int q0 = blockIdx.x * 64;
    const int tid = threadIdx.x;
    const int ty4 = (tid >> 4) * 4;
    const int tx  = tid & 15;
    const int tx4 = tx * 4, tx8 = tx * 8;
    const int lr = tid >> 2;           // 0..63 (loader row)
    const int lc = (tid & 3) * 32;     // loader col offset

    // --- load Q tile (pre-scaled) ---
    {
        int r = q0 + lr;
        if (r < S_LEN) {
            const float* src = g_q + (size_t)r * DIMN + h * HDN + lc;
#pragma unroll
            for (int u = 0; u < 8; u++) {
                float4 v = *(const float4*)(src + u * 4);
                Qs[lr * 132 + lc + u * 4 + 0] = v.x * QK_SCALE;
                Qs[lr * 132 + lc + u * 4 + 1] = v.y * QK_SCALE;
                Qs[lr * 132 + lc + u * 4 + 2] = v.z * QK_SCALE;
                Qs[lr * 132 + lc + u * 4 + 3] = v.w * QK_SCALE;
            }
        } else {
#pragma unroll
            for (int u = 0; u < 32; u++) Qs[lr * 132 + lc + u] = 0.f;
        }
    }

    float m_[4], l_[4];
    u64 acc[4][4];
#pragma unroll
    for (int i = 0; i < 4; i++) {
        m_[i] = -1e30f; l_[i] = 0.f;
#pragma unroll
        for (int d = 0; d < 4; d++) acc[i][d] = 0ull;
    }

    for (int kv0 = 0; kv0 < LKV; kv0 += 64) {
        __syncthreads();
        // --- load K,V tile ---
        {
            int pos = kv0 + lr;
            if (pos < LKV) {
                const float* ksrc;
                const float* vsrc;
                if (pos < CSTART) {
                    ksrc = cache_k + ((size_t)pos * NHN + h) * HDN + lc;
                    vsrc = cache_v + ((size_t)pos * NHN + h) * HDN + lc;
                } else {
                    ksrc = g_k + (size_t)(pos - CSTART) * DIMN + h * HDN + lc;
                    vsrc = g_v + (size_t)(pos - CSTART) * DIMN + h * HDN + lc;
                }
#pragma unroll
                for (int u = 0; u < 8; u++) {
                    *(float4*)&Ks[lr * 132 + lc + u * 4] = *(const float4*)(ksrc + u * 4);
                    *(float4*)&Vs[lr * 132 + lc + u * 4] = *(const float4*)(vsrc + u * 4);
                }
            } else {
#pragma unroll
                for (int u = 0; u < 32; u++) {
                    Ks[lr * 132 + lc + u] = 0.f;
                    Vs[lr * 132 + lc + u] = 0.f;
                }
            }
        }
        __syncthreads();

        // --- S = Q K^T (4x4 per thread) ---
        float s_[4][4];
#pragma unroll
        for (int i = 0; i < 4; i++)
#pragma unroll
            for (int j = 0; j < 4; j++) s_[i][j] = 0.f;

#pragma unroll 4
        for (int k = 0; k < HDN; k += 4) {
            float4 a[4], b[4];
#pragma unroll
            for (int i = 0; i < 4; i++) a[i] = *(const float4*)&Qs[(ty4 + i) * 132 + k];
#pragma unroll
            for (int j = 0; j < 4; j++) b[j] = *(const float4*)&Ks[(tx4 + j) * 132 + k];
#pragma unroll
            for (int i = 0; i < 4; i++)
#pragma unroll
                for (int j = 0; j < 4; j++) {
                    float t = s_[i][j];
                    t = fmaf(a[i].x, b[j].x, t);
                    t = fmaf(a[i].y, b[j].y, t);
                    t = fmaf(a[i].z, b[j].z, t);
                    t = fmaf(a[i].w, b[j].w, t);
                    s_[i][j] = t;
                }
        }

        // --- window-end mask ---
#pragma unroll
        for (int j = 0; j < 4; j++) {
            if (kv0 + tx4 + j >= LKV) {
#pragma unroll
                for (int i = 0; i < 4; i++) s_[i][j] = -1e30f;
            }
        }

        // --- online softmax ---
#pragma unroll
        for (int i = 0; i < 4; i++) {
            float mt = fmaxf(fmaxf(s_[i][0], s_[i][1]), fmaxf(s_[i][2], s_[i][3]));
#pragma unroll
            for (int off = 8; off; off >>= 1)
                mt = fmaxf(mt, __shfl_xor_sync(0xffffffffu, mt, off));
            float mn = fmaxf(m_[i], mt);
            float alpha = __expf(m_[i] - mn);
            m_[i] = mn;
            float rs = 0.f;
#pragma unroll
            for (int j = 0; j < 4; j++) {
                float p = __expf(s_[i][j] - mn);
                rs += p;
                Ps[(ty4 + i) * 68 + tx4 + j] = p;
            }
#pragma unroll
            for (int off = 8; off; off >>= 1)
                rs += __shfl_xor_sync(0xffffffffu, rs, off);
            l_[i] = l_[i] * alpha + rs;
            u64 A2 = splat2(alpha);
#pragma unroll
            for (int d = 0; d < 4; d++) acc[i][d] = f2mul(acc[i][d], A2);
        }
        __syncthreads();

        // --- O += P V  (f32x2 packed over d) ---
#pragma unroll 2
        for (int c = 0; c < 64; c++) {
            const u64* vp = (const u64*)&Vs[c * 132 + tx8];
            u64 v0 = vp[0], v1 = vp[1], v2 = vp[2], v3 = vp[3];
#pragma unroll
            for (int i = 0; i < 4; i++) {
                u64 p2 = splat2(Ps[(ty4 + i) * 68 + c]);
                acc[i][0] = f2fma(p2, v0, acc[i][0]);
                acc[i][1] = f2fma(p2, v1, acc[i][1]);
                acc[i][2] = f2fma(p2, v2, acc[i][2]);
                acc[i][3] = f2fma(p2, v3, acc[i][3]);
            }
        }
    }

    // --- epilogue: O /= l, write to g_o ---
#pragma unroll
    for (int i = 0; i < 4; i++) {
        int r = q0 + ty4 + i;
        if (r >= S_LEN) continue;
        float inv = 1.0f / l_[i];
        float o[8];
#pragma unroll
        for (int d = 0; d < 4; d++) {
            o[2 * d]     = f2lo(acc[i][d]) * inv;
            o[2 * d + 1] = f2hi(acc[i][d]) * inv;
        }
        float* dst = g_o + (size_t)r * DIMN + h * HDN + tx8;
        *(float4*)dst       = make_float4(o[0], o[1], o[2], o[3]);
        *(float4*)(dst + 4) = make_float4(o[4], o[5], o[6], o[7]);
    }
}

// =======================================================================
extern "C" void kernel_launch(void* const* d_in, const int* in_sizes, int n_in,
                              void* d_out, int out_size)
{
    (void)in_sizes; (void)n_in; (void)out_size;
    const float* x  = (const float*)d_in[0];
    const float* wq = (const float*)d_in[1];
    const float* bq = (const float*)d_in[2];
    const float* wk = (const float*)d_in[3];
    const float* bk = (const float*)d_in[4];
    const float* wv = (const float*)d_in[5];
    const float* bv = (const float*)d_in[6];
    const float* wo = (const float*)d_in[7];
    const float* bo = (const float*)d_in[8];
    const float* gq = (const float*)d_in[9];
    const float* gk = (const float*)d_in[10];
    const float* fc = (const float*)d_in[11];
    const float* fs = (const float*)d_in[12];
    const float* ck = (const float*)d_in[13];
    const float* cv = (const float*)d_in[14];
    float* out = (float*)d_out;

    cudaFuncSetAttribute(attn_kernel,
                         cudaFuncAttributeMaxDynamicSharedMemorySize, ATTN_SMEM);

    gemm_qkv<<<dim3(12, 13, 3), 256>>>(x, wq, bq, wk, bk, wv, bv);
    normrope_kernel<<<S_LEN, 256>>>(gq, gk, fc, fs);
    attn_kernel<<<dim3(25, NHN), 256, ATTN_SMEM>>>(ck, cv);
    gemm_out<<<dim3(12, 13), 256>>>(wo, bo, out);
}

// round 13
// speedup vs baseline: 1.0010x; 1.0010x over previous
#include <cuda_runtime.h>
#include <cstdint>

#define S_LEN   1560
#define DIMN    1536
#define NHN     12
#define HDN     128
#define LKV     10920
#define CSTART  9360
#define QK_SCALE 0.08838834764831845f

typedef unsigned long long u64;

// ---------------- scratch (device globals; no allocations) ----------------
__device__ float g_q[S_LEN * DIMN];
__device__ float g_k[S_LEN * DIMN];
__device__ float g_v[S_LEN * DIMN];
__device__ float g_o[S_LEN * DIMN];

// ---------------- packed f32x2 helpers ----------------
__device__ __forceinline__ u64 f2fma(u64 a, u64 b, u64 c) {
    u64 d;
    asm("fma.rn.f32x2 %0, %1, %2, %3;" : "=l"(d) : "l"(a), "l"(b), "l"(c));
    return d;
}
__device__ __forceinline__ u64 f2mul(u64 a, u64 b) {
    u64 d;
    asm("mul.rn.f32x2 %0, %1, %2;" : "=l"(d) : "l"(a), "l"(b));
    return d;
}
__device__ __forceinline__ u64 splat2(float x) {
    u64 d; unsigned xi = __float_as_uint(x);
    asm("mov.b64 %0, {%1, %1};" : "=l"(d) : "r"(xi));
    return d;
}
__device__ __forceinline__ float f2lo(u64 v) { return __uint_as_float((unsigned)(v & 0xffffffffull)); }
__device__ __forceinline__ float f2hi(u64 v) { return __uint_as_float((unsigned)(v >> 32)); }

// =======================================================================
// NT GEMM: C[m][n] = sum_k A[m][k]*W[n][k] + bias[n]
// M=1560 (guarded), N=K=1536. 128x128x16 tile, 256 threads, 8x8 microkernel.
// =======================================================================
__device__ __forceinline__ void gemm_body(const float* __restrict__ A,
                                          const float* __restrict__ W,
                                          const float* __restrict__ bias,
                                          float* __restrict__ C)
{
    __shared__ float As[16][128];
    __shared__ float Bs[16][128];

    const int m0 = blockIdx.y * 128;
    const int n0 = blockIdx.x * 128;
    const int tid = threadIdx.x;
    const int ty = tid >> 4, tx = tid & 15;
    const int lr = tid >> 2;            // 0..63
    const int lk = (tid & 3) * 4;       // 0,4,8,12

    float c[8][8];
#pragma unroll
    for (int i = 0; i < 8; i++)
#pragma unroll
        for (int j = 0; j < 8; j++) c[i][j] = 0.f;

    for (int k0 = 0; k0 < DIMN; k0 += 16) {
#pragma unroll
        for (int q = 0; q < 2; q++) {
            int m = m0 + lr + q * 64;
            float4 va = (m < S_LEN) ? *(const float4*)(A + (size_t)m * DIMN + k0 + lk)
                                    : make_float4(0.f, 0.f, 0.f, 0.f);
            As[lk + 0][lr + q * 64] = va.x;
            As[lk + 1][lr + q * 64] = va.y;
            As[lk + 2][lr + q * 64] = va.z;
            As[lk + 3][lr + q * 64] = va.w;
            int n = n0 + lr + q * 64;
            float4 vb = *(const float4*)(W + (size_t)n * DIMN + k0 + lk);
            Bs[lk + 0][lr + q * 64] = vb.x;
            Bs[lk + 1][lr + q * 64] = vb.y;
            Bs[lk + 2][lr + q * 64] = vb.z;
            Bs[lk + 3][lr + q * 64] = vb.w;
        }
        __syncthreads();
#pragma unroll
        for (int kk = 0; kk < 16; kk++) {
            float a[8], b[8];
            *(float4*)&a[0] = *(const float4*)&As[kk][ty * 8];
            *(float4*)&a[4] = *(const float4*)&As[kk][ty * 8 + 4];
            *(float4*)&b[0] = *(const float4*)&Bs[kk][tx * 8];
            *(float4*)&b[4] = *(const float4*)&Bs[kk][tx * 8 + 4];
#pragma unroll
            for (int i = 0; i < 8; i++)
#pragma unroll
                for (int j = 0; j < 8; j++)
                    c[i][j] = fmaf(a[i], b[j], c[i][j]);
        }
        __syncthreads();
    }

    float4 bia = *(const float4*)(bias + n0 + tx * 8);
    float4 bib = *(const float4*)(bias + n0 + tx * 8 + 4);
#pragma unroll
    for (int i = 0; i < 8; i++) {
        int m = m0 + ty * 8 + i;
        if (m >= S_LEN) continue;
        float4 r0 = make_float4(c[i][0] + bia.x, c[i][1] + bia.y,
                                c[i][2] + bia.z, c[i][3] + bia.w);
        float4 r1 = make_float4(c[i][4] + bib.x, c[i][5] + bib.y,
                                c[i][6] + bib.z, c[i][7] + bib.w);
        *(float4*)(C + (size_t)m * DIMN + n0 + tx * 8) = r0;
        *(float4*)(C + (size_t)m * DIMN + n0 + tx * 8 + 4) = r1;
    }
}

__global__ void __launch_bounds__(256) gemm_qkv(
    const float* __restrict__ x,
    const float* __restrict__ wq, const float* __restrict__ bq,
    const float* __restrict__ wk, const float* __restrict__ bk,
    const float* __restrict__ wv, const float* __restrict__ bv)
{
    const float* W; const float* B; float* C;
    if (blockIdx.z == 0)      { W = wq; B = bq; C = g_q; }
    else if (blockIdx.z == 1) { W = wk; B = bk; C = g_k; }
    else                      { W = wv; B = bv; C = g_v; }
    gemm_body(x, W, B, C);
}

__global__ void __launch_bounds__(256) gemm_out(
    const float* __restrict__ wo, const float* __restrict__ bo,
    float* __restrict__ out)
{
    gemm_body(g_o, wo, bo, out);
}

// =======================================================================
// rmsnorm(1536) + 3-band RoPE, one block per token, in-place on g_q/g_k.
// token s: f=0, h=s/52, w=s%52; c<22 -> row 6, c<43 -> row h, else row w.
// =======================================================================
__global__ void __launch_bounds__(256) normrope_kernel(
    const float* __restrict__ gq, const float* __restrict__ gk,
    const float* __restrict__ fcos, const float* __restrict__ fsin)
{
    const int s = blockIdx.x;
    float* qr = g_q + (size_t)s * DIMN;
    float* kr = g_k + (size_t)s * DIMN;
    const int tid = threadIdx.x;

    float sq = 0.f, sk = 0.f;
#pragma unroll
    for (int u = 0; u < 6; u++) {
        float a = qr[tid + u * 256]; sq = fmaf(a, a, sq);
        float b = kr[tid + u * 256]; sk = fmaf(b, b, sk);
    }
#pragma unroll
    for (int off = 16; off; off >>= 1) {
        sq += __shfl_xor_sync(0xffffffffu, sq, off);
        sk += __shfl_xor_sync(0xffffffffu, sk, off);
    }
    __shared__ float red[2][8];
    if ((tid & 31) == 0) { red[0][tid >> 5] = sq; red[1][tid >> 5] = sk; }
    __syncthreads();
    float tq = 0.f, tk = 0.f;
#pragma unroll
    for (int w = 0; w < 8; w++) { tq += red[0][w]; tk += red[1][w]; }
    const float invq = rsqrtf(tq * (1.0f / DIMN) + 1e-6f);
    const float invk = rsqrtf(tk * (1.0f / DIMN) + 1e-6f);

    const int h_tok = s / 52;
    const int w_tok = s - h_tok * 52;

#pragma unroll
    for (int p = tid; p < NHN * 64; p += 256) {
        int hh = p >> 6;
        int c = p & 63;
        int r = (c < 22) ? 6 : ((c < 43) ? h_tok : w_tok);
        float cs = fcos[r * 64 + c];
        float sn = fsin[r * 64 + c];
        int idx = hh * HDN + 2 * c;

        float qe = qr[idx] * invq * gq[idx];
        float qo = qr[idx + 1] * invq * gq[idx + 1];
        qr[idx]     = qe * cs - qo * sn;
        qr[idx + 1] = qe * sn + qo * cs;

        float ke = kr[idx] * invk * gk[idx];
        float ko = kr[idx + 1] * invk * gk[idx + 1];
        kr[idx]     = ke * cs - ko * sn;
        kr[idx + 1] = ke * sn + ko * cs;
    }
}

// =======================================================================
// Flash attention: grid (25 q-tiles, 12 heads), 256 threads, 64x64 tiles.
// Keys/values: pos < 9360 from cache, else from roped g_k / g_v.
// Dyn smem: Qs/Ks/Vs 64x132 + Ps 64x68 = 118784 B.
// =======================================================================
#define ATTN_SMEM ((3 * 64 * 132 + 64 * 68) * 4)

__global__ void __launch_bounds__(256) attn_kernel(
    const float* __restrict__ cache_k, const float* __restrict__ cache_v)
{
    extern __shared__ float sm[];
    float* Qs = sm;                    // 64 x 132
    float* Ks = Qs + 64 * 132;
    float* Vs = Ks + 64 * 132;
    float* Ps = Vs + 64 * 132;         // 64 x 68

    const int h  = blockIdx.y;
    const int q0 = blockIdx.x * 64;
    const int tid = threadIdx.x;
    const int ty4 = (tid >> 4) * 4;
    const int tx  = tid & 15;
    const int tx4 = tx * 4, tx8 = tx * 8;
    const int lr = tid >> 2;           // 0..63 (loader row)
    const int lc = (tid & 3) * 32;     // loader col offset

    // --- load Q tile (pre-scaled) ---
    {
        int r = q0 + lr;
        if (r < S_LEN) {
            const float* src = g_q + (size_t)r * DIMN + h * HDN + lc;
#pragma unroll
            for (int u = 0; u < 8; u++) {
                float4 v = *(const float4*)(src + u * 4);
                Qs[lr * 132 + lc + u * 4 + 0] = v.x * QK_SCALE;
                Qs[lr * 132 + lc + u * 4 + 1] = v.y * QK_SCALE;
                Qs[lr * 132 + lc + u * 4 + 2] = v.z * QK_SCALE;
                Qs[lr * 132 + lc + u * 4 + 3] = v.w * QK_SCALE;
            }
        } else {
#pragma unroll
            for (int u = 0; u < 32; u++) Qs[lr * 132 + lc + u] = 0.f;
        }
    }

    float m_[4], l_[4];
    u64 acc[4][4];
#pragma unroll
    for (int i = 0; i < 4; i++) {
        m_[i] = -1e30f; l_[i] = 0.f;
#pragma unroll
        for (int d = 0; d < 4; d++) acc[i][d] = 0ull;
    }

    for (int kv0 = 0; kv0 < LKV; kv0 += 64) {
        __syncthreads();
        // --- load K,V tile ---
        {
            int pos = kv0 + lr;
            if (pos < LKV) {
                const float* ksrc;
                const float* vsrc;
                if (pos < CSTART) {
                    ksrc = cache_k + ((size_t)pos * NHN + h) * HDN + lc;
                    vsrc = cache_v + ((size_t)pos * NHN + h) * HDN + lc;
                } else {
                    ksrc = g_k + (size_t)(pos - CSTART) * DIMN + h * HDN + lc;
                    vsrc = g_v + (size_t)(pos - CSTART) * DIMN + h * HDN + lc;
                }
#pragma unroll
                for (int u = 0; u < 8; u++) {
                    *(float4*)&Ks[lr * 132 + lc + u * 4] = *(const float4*)(ksrc + u * 4);
                    *(float4*)&Vs[lr * 132 + lc + u * 4] = *(const float4*)(vsrc + u * 4);
                }
            } else {
#pragma unroll
                for (int u = 0; u < 32; u++) {
                    Ks[lr * 132 + lc + u] = 0.f;
                    Vs[lr * 132 + lc + u] = 0.f;
                }
            }
        }
        __syncthreads();

        // --- S = Q K^T (4x4 per thread) ---
        float s_[4][4];
#pragma unroll
        for (int i = 0; i < 4; i++)
#pragma unroll
            for (int j = 0; j < 4; j++) s_[i][j] = 0.f;

#pragma unroll 4
        for (int k = 0; k < HDN; k += 4) {
            float4 a[4], b[4];
#pragma unroll
            for (int i = 0; i < 4; i++) a[i] = *(const float4*)&Qs[(ty4 + i) * 132 + k];
#pragma unroll
            for (int j = 0; j < 4; j++) b[j] = *(const float4*)&Ks[(tx4 + j) * 132 + k];
#pragma unroll
            for (int i = 0; i < 4; i++)
#pragma unroll
                for (int j = 0; j < 4; j++) {
                    float t = s_[i][j];
                    t = fmaf(a[i].x, b[j].x, t);
                    t = fmaf(a[i].y, b[j].y, t);
                    t = fmaf(a[i].z, b[j].z, t);
                    t = fmaf(a[i].w, b[j].w, t);
                    s_[i][j] = t;
                }
        }

        // --- window-end mask ---
#pragma unroll
        for (int j = 0; j < 4; j++) {
            if (kv0 + tx4 + j >= LKV) {
#pragma unroll
                for (int i = 0; i < 4; i++) s_[i][j] = -1e30f;
            }
        }

        // --- online softmax ---
#pragma unroll
        for (int i = 0; i < 4; i++) {
            float mt = fmaxf(fmaxf(s_[i][0], s_[i][1]), fmaxf(s_[i][2], s_[i][3]));
#pragma unroll
            for (int off = 8; off; off >>= 1)
                mt = fmaxf(mt, __shfl_xor_sync(0xffffffffu, mt, off));
            float mn = fmaxf(m_[i], mt);
            float alpha = __expf(m_[i] - mn);
            m_[i] = mn;
            float rs = 0.f;
#pragma unroll
            for (int j = 0; j < 4; j++) {
                float p = __expf(s_[i][j] - mn);
                rs += p;
                Ps[(ty4 + i) * 68 + tx4 + j] = p;
            }
#pragma unroll
            for (int off = 8; off; off >>= 1)
                rs += __shfl_xor_sync(0xffffffffu, rs, off);
            l_[i] = l_[i] * alpha + rs;
            u64 A2 = splat2(alpha);
#pragma unroll
            for (int d = 0; d < 4; d++) acc[i][d] = f2mul(acc[i][d], A2);
        }
        __syncthreads();

        // --- O += P V  (f32x2 packed over d) ---
#pragma unroll 2
        for (int c = 0; c < 64; c++) {
            const u64* vp = (const u64*)&Vs[c * 132 + tx8];
            u64 v0 = vp[0], v1 = vp[1], v2 = vp[2], v3 = vp[3];
#pragma unroll
            for (int i = 0; i < 4; i++) {
                u64 p2 = splat2(Ps[(ty4 + i) * 68 + c]);
                acc[i][0] = f2fma(p2, v0, acc[i][0]);
                acc[i][1] = f2fma(p2, v1, acc[i][1]);
                acc[i][2] = f2fma(p2, v2, acc[i][2]);
                acc[i][3] = f2fma(p2, v3, acc[i][3]);
            }
        }
    }

    // --- epilogue: O /= l, write to g_o ---
#pragma unroll
    for (int i = 0; i < 4; i++) {
        int r = q0 + ty4 + i;
        if (r >= S_LEN) continue;
        float inv = 1.0f / l_[i];
        float o[8];
#pragma unroll
        for (int d = 0; d < 4; d++) {
            o[2 * d]     = f2lo(acc[i][d]) * inv;
            o[2 * d + 1] = f2hi(acc[i][d]) * inv;
        }
        float* dst = g_o + (size_t)r * DIMN + h * HDN + tx8;
        *(float4*)dst       = make_float4(o[0], o[1], o[2], o[3]);
        *(float4*)(dst + 4) = make_float4(o[4], o[5], o[6], o[7]);
    }
}

// =======================================================================
extern "C" void kernel_launch(void* const* d_in, const int* in_sizes, int n_in,
                              void* d_out, int out_size)
{
    (void)in_sizes; (void)n_in; (void)out_size;
    const float* x  = (const float*)d_in[0];
    const float* wq = (const float*)d_in[1];
    const float* bq = (const float*)d_in[2];
    const float* wk = (const float*)d_in[3];
    const float* bk = (const float*)d_in[4];
    const float* wv = (const float*)d_in[5];
    const float* bv = (const float*)d_in[6];
    const float* wo = (const float*)d_in[7];
    const float* bo = (const float*)d_in[8];
    const float* gq = (const float*)d_in[9];
    const float* gk = (const float*)d_in[10];
    const float* fc = (const float*)d_in[11];
    const float* fs = (const float*)d_in[12];
    const float* ck = (const float*)d_in[13];
    const float* cv = (const float*)d_in[14];
    float* out = (float*)d_out;

    cudaFuncSetAttribute(attn_kernel,
                         cudaFuncAttributeMaxDynamicSharedMemorySize, ATTN_SMEM);

    gemm_qkv<<<dim3(12, 13, 3), 256>>>(x, wq, bq, wk, bk, wv, bv);
    normrope_kernel<<<S_LEN, 256>>>(gq, gk, fc, fs);
    attn_kernel<<<dim3(25, NHN), 256, ATTN_SMEM>>>(ck, cv);
    gemm_out<<<dim3(12, 13), 256>>>(wo, bo, out);
}

// round 14
// speedup vs baseline: 1.0818x; 1.0807x over previous
#include <cuda_runtime.h>
#include <cstdint>

#define S_LEN   1560
#define DIMN    1536
#define NHN     12
#define HDN     128
#define LKV     10920
#define CSTART  9360
#define QK_SCALE 0.08838834764831845f

typedef unsigned long long u64;

// ---------------- scratch (device globals; no allocations) ----------------
__device__ float g_q[S_LEN * DIMN];
__device__ float g_k[S_LEN * DIMN];
__device__ float g_v[S_LEN * DIMN];
__device__ float g_o[S_LEN * DIMN];

// ---------------- packed f32x2 helpers ----------------
__device__ __forceinline__ u64 f2fma(u64 a, u64 b, u64 c) {
    u64 d;
    asm("fma.rn.f32x2 %0, %1, %2, %3;" : "=l"(d) : "l"(a), "l"(b), "l"(c));
    return d;
}
__device__ __forceinline__ u64 f2mul(u64 a, u64 b) {
    u64 d;
    asm("mul.rn.f32x2 %0, %1, %2;" : "=l"(d) : "l"(a), "l"(b));
    return d;
}
__device__ __forceinline__ u64 splat2(float x) {
    u64 d; unsigned xi = __float_as_uint(x);
    asm("mov.b64 %0, {%1, %1};" : "=l"(d) : "r"(xi));
    return d;
}
__device__ __forceinline__ float f2lo(u64 v) { return __uint_as_float((unsigned)(v & 0xffffffffull)); }
__device__ __forceinline__ float f2hi(u64 v) { return __uint_as_float((unsigned)(v >> 32)); }

__device__ __forceinline__ void cp16(uint32_t dst, const float* src) {
    asm volatile("cp.async.cg.shared.global [%0], [%1], 16;\n"
                 :: "r"(dst), "l"(__cvta_generic_to_global((const void*)src)));
}

// =======================================================================
// NT GEMM: C[m][n] = sum_k A[m][k]*W[n][k] + bias[n]
// 128x128x16 tile, 256 threads, 8x8 microkernel via f32x2, reg prefetch.
// =======================================================================
__device__ __forceinline__ void gemm_body(const float* __restrict__ A,
                                          const float* __restrict__ W,
                                          const float* __restrict__ bias,
                                          float* __restrict__ C)
{
    __shared__ float As[16][128];
    __shared__ float Bs[16][128];

    const int m0 = blockIdx.y * 128;
    const int n0 = blockIdx.x * 128;
    const int tid = threadIdx.x;
    const int ty = tid >> 4, tx = tid & 15;
    const int lr = tid >> 2;            // 0..63
    const int lk = (tid & 3) * 4;       // 0,4,8,12

    u64 c2[8][4];
#pragma unroll
    for (int i = 0; i < 8; i++)
#pragma unroll
        for (int j = 0; j < 4; j++) c2[i][j] = 0ull;

    float4 ra[2], rb[2];
#pragma unroll
    for (int q = 0; q < 2; q++) {
        int m = m0 + lr + q * 64;
        ra[q] = (m < S_LEN) ? *(const float4*)(A + (size_t)m * DIMN + lk)
                            : make_float4(0.f, 0.f, 0.f, 0.f);
        int n = n0 + lr + q * 64;
        rb[q] = *(const float4*)(W + (size_t)n * DIMN + lk);
    }

    const int KT = DIMN / 16;  // 96
    for (int kt = 0; kt < KT; kt++) {
#pragma unroll
        for (int q = 0; q < 2; q++) {
            As[lk + 0][lr + q * 64] = ra[q].x;
            As[lk + 1][lr + q * 64] = ra[q].y;
            As[lk + 2][lr + q * 64] = ra[q].z;
            As[lk + 3][lr + q * 64] = ra[q].w;
            Bs[lk + 0][lr + q * 64] = rb[q].x;
            Bs[lk + 1][lr + q * 64] = rb[q].y;
            Bs[lk + 2][lr + q * 64] = rb[q].z;
            Bs[lk + 3][lr + q * 64] = rb[q].w;
        }
        __syncthreads();
        if (kt + 1 < KT) {
            int kb = (kt + 1) * 16 + lk;
#pragma unroll
            for (int q = 0; q < 2; q++) {
                int m = m0 + lr + q * 64;
                ra[q] = (m < S_LEN) ? *(const float4*)(A + (size_t)m * DIMN + kb)
                                    : make_float4(0.f, 0.f, 0.f, 0.f);
                int n = n0 + lr + q * 64;
                rb[q] = *(const float4*)(W + (size_t)n * DIMN + kb);
            }
        }
#pragma unroll
        for (int kk = 0; kk < 16; kk++) {
            float a[8];
            *(float4*)&a[0] = *(const float4*)&As[kk][ty * 8];
            *(float4*)&a[4] = *(const float4*)&As[kk][ty * 8 + 4];
            ulonglong2 b0 = *(const ulonglong2*)&Bs[kk][tx * 8];
            ulonglong2 b1 = *(const ulonglong2*)&Bs[kk][tx * 8 + 4];
#pragma unroll
            for (int i = 0; i < 8; i++) {
                u64 ai = splat2(a[i]);
                c2[i][0] = f2fma(ai, b0.x, c2[i][0]);
                c2[i][1] = f2fma(ai, b0.y, c2[i][1]);
                c2[i][2] = f2fma(ai, b1.x, c2[i][2]);
                c2[i][3] = f2fma(ai, b1.y, c2[i][3]);
            }
        }
        __syncthreads();
    }

    float4 bia = *(const float4*)(bias + n0 + tx * 8);
    float4 bib = *(const float4*)(bias + n0 + tx * 8 + 4);
#pragma unroll
    for (int i = 0; i < 8; i++) {
        int m = m0 + ty * 8 + i;
        if (m >= S_LEN) continue;
        float4 r0 = make_float4(f2lo(c2[i][0]) + bia.x, f2hi(c2[i][0]) + bia.y,
                                f2lo(c2[i][1]) + bia.z, f2hi(c2[i][1]) + bia.w);
        float4 r1 = make_float4(f2lo(c2[i][2]) + bib.x, f2hi(c2[i][2]) + bib.y,
                                f2lo(c2[i][3]) + bib.z, f2hi(c2[i][3]) + bib.w);
        *(float4*)(C + (size_t)m * DIMN + n0 + tx * 8) = r0;
        *(float4*)(C + (size_t)m * DIMN + n0 + tx * 8 + 4) = r1;
    }
}

__global__ void __launch_bounds__(256) gemm_qkv(
    const float* __restrict__ x,
    const float* __restrict__ wq, const float* __restrict__ bq,
    const float* __restrict__ wk, const float* __restrict__ bk,
    const float* __restrict__ wv, const float* __restrict__ bv)
{
    const float* W; const float* B; float* C;
    if (blockIdx.z == 0)      { W = wq; B = bq; C = g_q; }
    else if (blockIdx.z == 1) { W = wk; B = bk; C = g_k; }
    else                      { W = wv; B = bv; C = g_v; }
    gemm_body(x, W, B, C);
}

__global__ void __launch_bounds__(256) gemm_out(
    const float* __restrict__ wo, const float* __restrict__ bo,
    float* __restrict__ out)
{
    gemm_body(g_o, wo, bo, out);
}

// =======================================================================
// rmsnorm(1536) + 3-band RoPE, one block per token, in-place on g_q/g_k.
// =======================================================================
__global__ void __launch_bounds__(256) normrope_kernel(
    const float* __restrict__ gq, const float* __restrict__ gk,
    const float* __restrict__ fcos, const float* __restrict__ fsin)
{
    const int s = blockIdx.x;
    float* qr = g_q + (size_t)s * DIMN;
    float* kr = g_k + (size_t)s * DIMN;
    const int tid = threadIdx.x;

    float sq = 0.f, sk = 0.f;
#pragma unroll
    for (int u = 0; u < 6; u++) {
        float a = qr[tid + u * 256]; sq = fmaf(a, a, sq);
        float b = kr[tid + u * 256]; sk = fmaf(b, b, sk);
    }
#pragma unroll
    for (int off = 16; off; off >>= 1) {
        sq += __shfl_xor_sync(0xffffffffu, sq, off);
        sk += __shfl_xor_sync(0xffffffffu, sk, off);
    }
    __shared__ float red[2][8];
    if ((tid & 31) == 0) { red[0][tid >> 5] = sq; red[1][tid >> 5] = sk; }
    __syncthreads();
    float tq = 0.f, tk = 0.f;
#pragma unroll
    for (int w = 0; w < 8; w++) { tq += red[0][w]; tk += red[1][w]; }
    const float invq = rsqrtf(tq * (1.0f / DIMN) + 1e-6f);
    const float invk = rsqrtf(tk * (1.0f / DIMN) + 1e-6f);

    const int h_tok = s / 52;
    const int w_tok = s - h_tok * 52;

#pragma unroll
    for (int p = tid; p < NHN * 64; p += 256) {
        int hh = p >> 6;
        int c = p & 63;
        int r = (c < 22) ? 6 : ((c < 43) ? h_tok : w_tok);
        float cs = fcos[r * 64 + c];
        float sn = fsin[r * 64 + c];
        int idx = hh * HDN + 2 * c;

        float qe = qr[idx] * invq * gq[idx];
        float qo = qr[idx + 1] * invq * gq[idx + 1];
        qr[idx]     = qe * cs - qo * sn;
        qr[idx + 1] = qe * sn + qo * cs;

        float ke = kr[idx] * invk * gk[idx];
        float ko = kr[idx + 1] * invk * gk[idx + 1];
        kr[idx]     = ke * cs - ko * sn;
        kr[idx + 1] = ke * sn + ko * cs;
    }
}

// =======================================================================
// Flash attention, 64x64 tiles, cp.async double-buffered K/V, f32x2 math.
// grid (25 q-tiles, 12 heads), 256 threads.
// Dyn smem: Q 64x132 + 2x(K 64x132) + 2x(V 64x132) + P 64x68 = 186368 B.
// =======================================================================
#define KV_STRIDE (64 * 132)
#define ATTN_SMEM ((KV_STRIDE * 5 + 64 * 68) * 4)

__global__ void __launch_bounds__(256) attn_kernel(
    const float* __restrict__ cache_k, const float* __restrict__ cache_v)
{
    extern __shared__ __align__(16) float sm[];
    float* Qs = sm;                        // 64 x 132
    float* Ks = Qs + KV_STRIDE;            // 2 stages
    float* Vs = Ks + 2 * KV_STRIDE;        // 2 stages
    float* Ps = Vs + 2 * KV_STRIDE;        // 64 x 68

    const int h  = blockIdx.y;
    const int q0 = blockIdx.x * 64;
    const int tid = threadIdx.x;
    const int ty4 = (tid >> 4) * 4;
    const int tx  = tid & 15;
    const int tx4 = tx * 4, tx8 = tx * 8;
    const int lr = tid >> 2;               // loader row 0..63
    const int lc = (tid & 3) * 32;         // loader col offset (floats)

    const uint32_t kbase = (uint32_t)__cvta_generic_to_shared(Ks) + (lr * 132 + lc) * 4;
    const uint32_t vbase = (uint32_t)__cvta_generic_to_shared(Vs) + (lr * 132 + lc) * 4;

    // --- load Q tile (pre-scaled) ---
    {
        int r = q0 + lr;
        if (r < S_LEN) {
            const float* src = g_q + (size_t)r * DIMN + h * HDN + lc;
#pragma unroll
            for (int u = 0; u < 8; u++) {
                float4 v = *(const float4*)(src + u * 4);
                Qs[lr * 132 + lc + u * 4 + 0] = v.x * QK_SCALE;
                Qs[lr * 132 + lc + u * 4 + 1] = v.y * QK_SCALE;
                Qs[lr * 132 + lc + u * 4 + 2] = v.z * QK_SCALE;
                Qs[lr * 132 + lc + u * 4 + 3] = v.w * QK_SCALE;
            }
        } else {
#pragma unroll
            for (int u = 0; u < 32; u++) Qs[lr * 132 + lc + u] = 0.f;
        }
    }

    float m_[4], l_[4];
    u64 acc[4][4];
#pragma unroll
    for (int i = 0; i < 4; i++) {
        m_[i] = -1e30f; l_[i] = 0.f;
#pragma unroll
        for (int d = 0; d < 4; d++) acc[i][d] = 0ull;
    }

    const int NT = (LKV + 63) / 64;        // 171

    // issue tile 0
    {
        int pos = lr;  // kv0 = 0, always < CSTART
        const float* ksrc = cache_k + ((size_t)pos * NHN + h) * HDN + lc;
        const float* vsrc = cache_v + ((size_t)pos * NHN + h) * HDN + lc;
#pragma unroll
        for (int u = 0; u < 8; u++) {
            cp16(kbase + u * 16, ksrc + u * 4);
            cp16(vbase + u * 16, vsrc + u * 4);
        }
        asm volatile("cp.async.commit_group;\n");
    }

    for (int t = 0; t < NT; t++) {
        const int cur = t & 1;
        const int kv0 = t * 64;

        if (t + 1 < NT) {
            // prefetch tile t+1 into stage cur^1
            int pos = kv0 + 64 + lr;
            if (pos < LKV) {
                const float* ksrc;
                const float* vsrc;
                if (pos < CSTART) {
                    ksrc = cache_k + ((size_t)pos * NHN + h) * HDN + lc;
                    vsrc = cache_v + ((size_t)pos * NHN + h) * HDN + lc;
                } else {
                    ksrc = g_k + (size_t)(pos - CSTART) * DIMN + h * HDN + lc;
                    vsrc = g_v + (size_t)(pos - CSTART) * DIMN + h * HDN + lc;
                }
                uint32_t kd = kbase + (cur ^ 1) * (KV_STRIDE * 4);
                uint32_t vd = vbase + (cur ^ 1) * (KV_STRIDE * 4);
#pragma unroll
                for (int u = 0; u < 8; u++) {
                    cp16(kd + u * 16, ksrc + u * 4);
                    cp16(vd + u * 16, vsrc + u * 4);
                }
            }
            asm volatile("cp.async.commit_group;\n");
            asm volatile("cp.async.wait_group 1;\n");
        } else {
            asm volatile("cp.async.wait_group 0;\n");
        }
        __syncthreads();

        const float* Kc = Ks + cur * KV_STRIDE;
        const float* Vc = Vs + cur * KV_STRIDE;

        // --- S = Q K^T, packed over k ---
        u64 s2[4][4];
#pragma unroll
        for (int i = 0; i < 4; i++)
#pragma unroll
            for (int j = 0; j < 4; j++) s2[i][j] = 0ull;

#pragma unroll 4
        for (int k = 0; k < HDN; k += 4) {
            ulonglong2 a[4], b[4];
#pragma unroll
            for (int i = 0; i < 4; i++)
                a[i] = *(const ulonglong2*)&Qs[(ty4 + i) * 132 + k];
#pragma unroll
            for (int j = 0; j < 4; j++)
                b[j] = *(const ulonglong2*)&Kc[(tx4 + j) * 132 + k];
#pragma unroll
            for (int i = 0; i < 4; i++)
#pragma unroll
                for (int j = 0; j < 4; j++) {
                    s2[i][j] = f2fma(a[i].x, b[j].x, s2[i][j]);
                    s2[i][j] = f2fma(a[i].y, b[j].y, s2[i][j]);
                }
        }

        float s_[4][4];
#pragma unroll
        for (int i = 0; i < 4; i++)
#pragma unroll
            for (int j = 0; j < 4; j++)
                s_[i][j] = f2lo(s2[i][j]) + f2hi(s2[i][j]);

        // --- window-end mask (tail tile) ---
        if (kv0 + 64 > LKV) {
#pragma unroll
            for (int j = 0; j < 4; j++) {
                if (kv0 + tx4 + j >= LKV) {
#pragma unroll
                    for (int i = 0; i < 4; i++) s_[i][j] = -1e30f;
                }
            }
        }

        // --- online softmax (per row group: 16 threads, same warp) ---
#pragma unroll
        for (int i = 0; i < 4; i++) {
            float mt = fmaxf(fmaxf(s_[i][0], s_[i][1]), fmaxf(s_[i][2], s_[i][3]));
#pragma unroll
            for (int off = 8; off; off >>= 1)
                mt = fmaxf(mt, __shfl_xor_sync(0xffffffffu, mt, off));
            float mn = fmaxf(m_[i], mt);
            float alpha = __expf(m_[i] - mn);
            m_[i] = mn;
            float rs = 0.f;
#pragma unroll
            for (int j = 0; j < 4; j++) {
                float p = __expf(s_[i][j] - mn);
                rs += p;
                Ps[(ty4 + i) * 68 + tx4 + j] = p;
            }
#pragma unroll
            for (int off = 8; off; off >>= 1)
                rs += __shfl_xor_sync(0xffffffffu, rs, off);
            l_[i] = l_[i] * alpha + rs;
            u64 A2 = splat2(alpha);
#pragma unroll
            for (int d = 0; d < 4; d++) acc[i][d] = f2mul(acc[i][d], A2);
        }
        __syncwarp();

        // --- O += P V  (f32x2 packed over d) ---
#pragma unroll 2
        for (int c0 = 0; c0 < 64; c0 += 4) {
            float4 p[4];
#pragma unroll
            for (int i = 0; i < 4; i++)
                p[i] = *(const float4*)&Ps[(ty4 + i) * 68 + c0];
#pragma unroll
            for (int cc = 0; cc < 4; cc++) {
                const ulonglong2* vp = (const ulonglong2*)&Vc[(c0 + cc) * 132 + tx8];
                ulonglong2 v0 = vp[0];
                ulonglong2 v1 = vp[1];
#pragma unroll
                for (int i = 0; i < 4; i++) {
                    float pv = (cc == 0) ? p[i].x : (cc == 1) ? p[i].y
                             : (cc == 2) ? p[i].z : p[i].w;
                    u64 p2 = splat2(pv);
                    acc[i][0] = f2fma(p2, v0.x, acc[i][0]);
                    acc[i][1] = f2fma(p2, v0.y, acc[i][1]);
                    acc[i][2] = f2fma(p2, v1.x, acc[i][2]);
                    acc[i][3] = f2fma(p2, v1.y, acc[i][3]);
                }
            }
        }
        __syncthreads();   // buffer `cur` free for prefetch of t+2
    }

    // --- epilogue: O /= l, write to g_o ---
#pragma unroll
    for (int i = 0; i < 4; i++) {
        int r = q0 + ty4 + i;
        if (r >= S_LEN) continue;
        float inv = 1.0f / l_[i];
        float o[8];
#pragma unroll
        for (int d = 0; d < 4; d++) {
            o[2 * d]     = f2lo(acc[i][d]) * inv;
            o[2 * d + 1] = f2hi(acc[i][d]) * inv;
        }
        float* dst = g_o + (size_t)r * DIMN + h * HDN + tx8;
        *(float4*)dst       = make_float4(o[0], o[1], o[2], o[3]);
        *(float4*)(dst + 4) = make_float4(o[4], o[5], o[6], o[7]);
    }
}

// =======================================================================
extern "C" void kernel_launch(void* const* d_in, const int* in_sizes, int n_in,
                              void* d_out, int out_size)
{
    (void)in_sizes; (void)n_in; (void)out_size;
    const float* x  = (const float*)d_in[0];
    const float* wq = (const float*)d_in[1];
    const float* bq = (const float*)d_in[2];
    const float* wk = (const float*)d_in[3];
    const float* bk = (const float*)d_in[4];
    const float* wv = (const float*)d_in[5];
    const float* bv = (const float*)d_in[6];
    const float* wo = (const float*)d_in[7];
    const float* bo = (const float*)d_in[8];
    const float* gq = (const float*)d_in[9];
    const float* gk = (const float*)d_in[10];
    const float* fc = (const float*)d_in[11];
    const float* fs = (const float*)d_in[12];
    const float* ck = (const float*)d_in[13];
    const float* cv = (const float*)d_in[14];
    float* out = (float*)d_out;

    cudaFuncSetAttribute(attn_kernel,
                         cudaFuncAttributeMaxDynamicSharedMemorySize, ATTN_SMEM);

    gemm_qkv<<<dim3(12, 13, 3), 256>>>(x, wq, bq, wk, bk, wv, bv);
    normrope_kernel<<<S_LEN, 256>>>(gq, gk, fc, fs);
    attn_kernel<<<dim3(25, NHN), 256, ATTN_SMEM>>>(ck, cv);
    gemm_out<<<dim3(12, 13), 256>>>(wo, bo, out);
}

// round 15
// speedup vs baseline: 1.6526x; 1.5276x over previous
#include <cuda_runtime.h>
#include <cstdint>

#define S_LEN   1560
#define DIMN    1536
#define NHN     12
#define HDN     128
#define LKV     10920
#define CSTART  9360
#define QK_SCALE 0.08838834764831845f

#define KV_TILE 128
#define NT_TILES ((LKV + KV_TILE - 1) / KV_TILE)   // 86
#define KSTR 132
#define PSTR 68

typedef unsigned long long u64;

// ---------------- scratch (device globals; no allocations) ----------------
__device__ float g_q[S_LEN * DIMN];
__device__ float g_k[S_LEN * DIMN];
__device__ float g_v[S_LEN * DIMN];
__device__ float g_o[S_LEN * DIMN];

// ---------------- packed f32x2 helpers ----------------
__device__ __forceinline__ u64 f2fma(u64 a, u64 b, u64 c) {
    u64 d;
    asm("fma.rn.f32x2 %0, %1, %2, %3;" : "=l"(d) : "l"(a), "l"(b), "l"(c));
    return d;
}
__device__ __forceinline__ u64 f2mul(u64 a, u64 b) {
    u64 d;
    asm("mul.rn.f32x2 %0, %1, %2;" : "=l"(d) : "l"(a), "l"(b));
    return d;
}
__device__ __forceinline__ u64 splat2(float x) {
    u64 d; unsigned xi = __float_as_uint(x);
    asm("mov.b64 %0, {%1, %1};" : "=l"(d) : "r"(xi));
    return d;
}
__device__ __forceinline__ u64 pack2(float lo, float hi) {
    u64 d;
    asm("mov.b64 %0, {%1, %2};" : "=l"(d) : "r"(__float_as_uint(lo)), "r"(__float_as_uint(hi)));
    return d;
}
__device__ __forceinline__ float f2lo(u64 v) { return __uint_as_float((unsigned)(v & 0xffffffffull)); }
__device__ __forceinline__ float f2hi(u64 v) { return __uint_as_float((unsigned)(v >> 32)); }

__device__ __forceinline__ void cp16(uint32_t dst, const float* src) {
    asm volatile("cp.async.cg.shared.global [%0], [%1], 16;\n"
                 :: "r"(dst), "l"(__cvta_generic_to_global((const void*)src)));
}

// =======================================================================
// NT GEMM: C[m][n] = sum_k A[m][k]*W[n][k] + bias[n]
// 128x64x16 tile, 256 threads, 8x4 microkernel, f2fma, reg prefetch.
// ~70 regs -> 2 CTAs/SM.
// =======================================================================
__device__ __forceinline__ void gemm_body(const float* __restrict__ A,
                                          const float* __restrict__ W,
                                          const float* __restrict__ bias,
                                          float* __restrict__ C)
{
    __shared__ float As[16][128];
    __shared__ float Bs[16][64];

    const int m0 = blockIdx.y * 128;
    const int n0 = blockIdx.x * 64;
    const int tid = threadIdx.x;
    const int ty = tid >> 4, tx = tid & 15;     // ty 0..15 (8 rows), tx 0..15 (4 cols)
    const int lrA = tid >> 2;                    // 0..63
    const int lkA = (tid & 3) * 4;               // 0,4,8,12

    u64 c2[8][2];
#pragma unroll
    for (int i = 0; i < 8; i++) { c2[i][0] = 0ull; c2[i][1] = 0ull; }

    float4 ra[2], rb;
#pragma unroll
    for (int q = 0; q < 2; q++) {
        int m = m0 + lrA + q * 64;
        ra[q] = (m < S_LEN) ? *(const float4*)(A + (size_t)m * DIMN + lkA)
                            : make_float4(0.f, 0.f, 0.f, 0.f);
    }
    rb = *(const float4*)(W + (size_t)(n0 + lrA) * DIMN + lkA);

    const int KT = DIMN / 16;
    for (int kt = 0; kt < KT; kt++) {
#pragma unroll
        for (int q = 0; q < 2; q++) {
            As[lkA + 0][lrA + q * 64] = ra[q].x;
            As[lkA + 1][lrA + q * 64] = ra[q].y;
            As[lkA + 2][lrA + q * 64] = ra[q].z;
            As[lkA + 3][lrA + q * 64] = ra[q].w;
        }
        Bs[lkA + 0][lrA] = rb.x;
        Bs[lkA + 1][lrA] = rb.y;
        Bs[lkA + 2][lrA] = rb.z;
        Bs[lkA + 3][lrA] = rb.w;
        __syncthreads();
        if (kt + 1 < KT) {
            int kb = (kt + 1) * 16 + lkA;
#pragma unroll
            for (int q = 0; q < 2; q++) {
                int m = m0 + lrA + q * 64;
                ra[q] = (m < S_LEN) ? *(const float4*)(A + (size_t)m * DIMN + kb)
                                    : make_float4(0.f, 0.f, 0.f, 0.f);
            }
            rb = *(const float4*)(W + (size_t)(n0 + lrA) * DIMN + kb);
        }
#pragma unroll
        for (int kk = 0; kk < 16; kk++) {
            float a[8];
            *(float4*)&a[0] = *(const float4*)&As[kk][ty * 8];
            *(float4*)&a[4] = *(const float4*)&As[kk][ty * 8 + 4];
            ulonglong2 b2 = *(const ulonglong2*)&Bs[kk][tx * 4];
#pragma unroll
            for (int i = 0; i < 8; i++) {
                u64 ai = splat2(a[i]);
                c2[i][0] = f2fma(ai, b2.x, c2[i][0]);
                c2[i][1] = f2fma(ai, b2.y, c2[i][1]);
            }
        }
        __syncthreads();
    }

    float4 bi = *(const float4*)(bias + n0 + tx * 4);
#pragma unroll
    for (int i = 0; i < 8; i++) {
        int m = m0 + ty * 8 + i;
        if (m >= S_LEN) continue;
        float4 r = make_float4(f2lo(c2[i][0]) + bi.x, f2hi(c2[i][0]) + bi.y,
                               f2lo(c2[i][1]) + bi.z, f2hi(c2[i][1]) + bi.w);
        *(float4*)(C + (size_t)m * DIMN + n0 + tx * 4) = r;
    }
}

__global__ void __launch_bounds__(256, 2) gemm_qkv(
    const float* __restrict__ x,
    const float* __restrict__ wq, const float* __restrict__ bq,
    const float* __restrict__ wk, const float* __restrict__ bk,
    const float* __restrict__ wv, const float* __restrict__ bv)
{
    const float* W; const float* B; float* C;
    if (blockIdx.z == 0)      { W = wq; B = bq; C = g_q; }
    else if (blockIdx.z == 1) { W = wk; B = bk; C = g_k; }
    else                      { W = wv; B = bv; C = g_v; }
    gemm_body(x, W, B, C);
}

__global__ void __launch_bounds__(256, 2) gemm_out(
    const float* __restrict__ wo, const float* __restrict__ bo,
    float* __restrict__ out)
{
    gemm_body(g_o, wo, bo, out);
}

// =======================================================================
// rmsnorm(1536) + 3-band RoPE, one block per token, in-place on g_q/g_k.
// =======================================================================
__global__ void __launch_bounds__(256) normrope_kernel(
    const float* __restrict__ gq, const float* __restrict__ gk,
    const float* __restrict__ fcos, const float* __restrict__ fsin)
{
    const int s = blockIdx.x;
    float* qr = g_q + (size_t)s * DIMN;
    float* kr = g_k + (size_t)s * DIMN;
    const int tid = threadIdx.x;

    float sq = 0.f, sk = 0.f;
#pragma unroll
    for (int u = 0; u < 6; u++) {
        float a = qr[tid + u * 256]; sq = fmaf(a, a, sq);
        float b = kr[tid + u * 256]; sk = fmaf(b, b, sk);
    }
#pragma unroll
    for (int off = 16; off; off >>= 1) {
        sq += __shfl_xor_sync(0xffffffffu, sq, off);
        sk += __shfl_xor_sync(0xffffffffu, sk, off);
    }
    __shared__ float red[2][8];
    if ((tid & 31) == 0) { red[0][tid >> 5] = sq; red[1][tid >> 5] = sk; }
    __syncthreads();
    float tq = 0.f, tk = 0.f;
#pragma unroll
    for (int w = 0; w < 8; w++) { tq += red[0][w]; tk += red[1][w]; }
    const float invq = rsqrtf(tq * (1.0f / DIMN) + 1e-6f);
    const float invk = rsqrtf(tk * (1.0f / DIMN) + 1e-6f);

    const int h_tok = s / 52;
    const int w_tok = s - h_tok * 52;

#pragma unroll
    for (int p = tid; p < NHN * 64; p += 256) {
        int hh = p >> 6;
        int c = p & 63;
        int r = (c < 22) ? 6 : ((c < 43) ? h_tok : w_tok);
        float cs = fcos[r * 64 + c];
        float sn = fsin[r * 64 + c];
        int idx = hh * HDN + 2 * c;

        float qe = qr[idx] * invq * gq[idx];
        float qo = qr[idx + 1] * invq * gq[idx + 1];
        qr[idx]     = qe * cs - qo * sn;
        qr[idx + 1] = qe * sn + qo * cs;

        float ke = kr[idx] * invk * gk[idx];
        float ko = kr[idx + 1] * invk * gk[idx + 1];
        kr[idx]     = ke * cs - ko * sn;
        kr[idx + 1] = ke * sn + ko * cs;
    }
}

// =======================================================================
// Flash attention v3: 64 q-rows x 128 kv per tile, 256 threads (8 warps).
// Warp w owns q-rows w*8..w*8+7; lane owns 4 kv-cols (QK) / 4 d-cols (PV).
// K(t+1) streams during softmax+PV(t); V(t+1) streams during QK(t+1).
// P stored transposed with row-pair packing -> f32x2 PV.
// smem: Q 64x128 + K 128x132 + V 128x132 + P^T 128x68 = 202752 B.
// =======================================================================
#define ATTN_SMEM ((64*128 + 2*128*KSTR + 128*PSTR) * 4)

__device__ __forceinline__ void issue_kv_tile(uint32_t base,
                                              const float* __restrict__ cache,
                                              const float* __restrict__ gnew,
                                              int t, int h, int tid)
{
    if (t < NT_TILES) {
        const int kv0 = t * KV_TILE;
#pragma unroll
        for (int j = 0; j < 16; j++) {
            int ch = j * 256 + tid;          // 0..4095
            int row = ch >> 5;               // 0..127
            int cc = (ch & 31) * 4;          // 0..124
            int pos = kv0 + row;
            if (pos > LKV - 1) pos = LKV - 1;
            const float* src = (pos < CSTART)
                ? cache + ((size_t)pos * NHN + h) * HDN + cc
                : gnew + (size_t)(pos - CSTART) * DIMN + h * HDN + cc;
            cp16(base + (unsigned)(row * KSTR + cc) * 4u, src);
        }
    }
    asm volatile("cp.async.commit_group;\n");
}

__global__ void __launch_bounds__(256) attn_kernel(
    const float* __restrict__ cache_k, const float* __restrict__ cache_v)
{
    extern __shared__ __align__(16) float sm[];
    float* Qs = sm;                      // 64 x 128
    float* Ks = Qs + 64 * 128;           // 128 x 132
    float* Vs = Ks + 128 * KSTR;         // 128 x 132
    float* Ps = Vs + 128 * KSTR;         // 128 x 68 (transposed P: [c][r])

    const int h  = blockIdx.y;
    const int q0 = blockIdx.x * 64;
    const int tid = threadIdx.x;
    const int w = tid >> 5;              // warp 0..7
    const int lane = tid & 31;
    const int r0 = w * 8;                // q-row base within tile
    const int c0 = lane * 4;             // kv-col base (QK) / d base (PV)

    const uint32_t kb = (uint32_t)__cvta_generic_to_shared(Ks);
    const uint32_t vb = (uint32_t)__cvta_generic_to_shared(Vs);

    // --- load Q tile (pre-scaled) ---
    {
        int qr = tid >> 2;
        int qc = (tid & 3) * 32;
        int r = q0 + qr;
        float* dst = Qs + qr * 128 + qc;
        if (r < S_LEN) {
            const float* src = g_q + (size_t)r * DIMN + h * HDN + qc;
#pragma unroll
            for (int u = 0; u < 8; u++) {
                float4 v = *(const float4*)(src + u * 4);
                dst[u * 4 + 0] = v.x * QK_SCALE;
                dst[u * 4 + 1] = v.y * QK_SCALE;
                dst[u * 4 + 2] = v.z * QK_SCALE;
                dst[u * 4 + 3] = v.w * QK_SCALE;
            }
        } else {
#pragma unroll
            for (int u = 0; u < 32; u++) dst[u] = 0.f;
        }
    }

    float m_[8], l_[8];
    u64 O2[4][4];
#pragma unroll
    for (int i = 0; i < 8; i++) { m_[i] = -1e30f; l_[i] = 0.f; }
#pragma unroll
    for (int p = 0; p < 4; p++)
#pragma unroll
        for (int d = 0; d < 4; d++) O2[p][d] = 0ull;

    issue_kv_tile(kb, cache_k, g_k, 0, h, tid);
    issue_kv_tile(vb, cache_v, g_v, 0, h, tid);

    for (int t = 0; t < NT_TILES; t++) {
        // K(t) ready (newest pending group: V(t))
        asm volatile("cp.async.wait_group 1;\n");
        __syncthreads();

        // --- S = Q K^T, k-packed f32x2, 8x4 per thread ---
        u64 s2[8][4];
#pragma unroll
        for (int i = 0; i < 8; i++)
#pragma unroll
            for (int j = 0; j < 4; j++) s2[i][j] = 0ull;

#pragma unroll 2
        for (int k = 0; k < HDN; k += 4) {
            ulonglong2 b[4];
#pragma unroll
            for (int j = 0; j < 4; j++)
                b[j] = *(const ulonglong2*)&Ks[(c0 + j) * KSTR + k];
#pragma unroll
            for (int i = 0; i < 8; i++) {
                ulonglong2 a = *(const ulonglong2*)&Qs[(r0 + i) * 128 + k];
#pragma unroll
                for (int j = 0; j < 4; j++) {
                    s2[i][j] = f2fma(a.x, b[j].x, s2[i][j]);
                    s2[i][j] = f2fma(a.y, b[j].y, s2[i][j]);
                }
            }
        }

        float s_[8][4];
#pragma unroll
        for (int i = 0; i < 8; i++)
#pragma unroll
            for (int j = 0; j < 4; j++)
                s_[i][j] = f2lo(s2[i][j]) + f2hi(s2[i][j]);

        // mask tail tile
        if (t == NT_TILES - 1) {
            const int kv0 = t * KV_TILE;
#pragma unroll
            for (int j = 0; j < 4; j++) {
                if (kv0 + c0 + j >= LKV) {
#pragma unroll
                    for (int i = 0; i < 8; i++) s_[i][j] = -1e30f;
                }
            }
        }

        // all warps done reading Ks -> stream K(t+1)
        __syncthreads();
        issue_kv_tile(kb, cache_k, g_k, t + 1, h, tid);

        // --- online softmax (full-warp: all 32 lanes share rows) ---
        float al[8];
#pragma unroll
        for (int i = 0; i < 8; i++) {
            float mt = fmaxf(fmaxf(s_[i][0], s_[i][1]), fmaxf(s_[i][2], s_[i][3]));
#pragma unroll
            for (int off = 16; off; off >>= 1)
                mt = fmaxf(mt, __shfl_xor_sync(0xffffffffu, mt, off));
            float mn = fmaxf(m_[i], mt);
            al[i] = __expf(m_[i] - mn);
            m_[i] = mn;
            float rs = 0.f;
#pragma unroll
            for (int j = 0; j < 4; j++) {
                float p = __expf(s_[i][j] - mn);
                s_[i][j] = p;
                rs += p;
            }
#pragma unroll
            for (int off = 16; off; off >>= 1)
                rs += __shfl_xor_sync(0xffffffffu, rs, off);
            l_[i] = l_[i] * al[i] + rs;
        }
        // rescale accumulators (row-pair packed)
#pragma unroll
        for (int p = 0; p < 4; p++) {
            u64 a2 = pack2(al[2 * p], al[2 * p + 1]);
#pragma unroll
            for (int d = 0; d < 4; d++) O2[p][d] = f2mul(O2[p][d], a2);
        }
        // write P^T with row-pair packing: Ps[c][r], u64 covers rows (2p,2p+1)
#pragma unroll
        for (int j = 0; j < 4; j++) {
#pragma unroll
            for (int p = 0; p < 4; p++) {
                u64 pw = pack2(s_[2 * p][j], s_[2 * p + 1][j]);
                *(u64*)&Ps[(c0 + j) * PSTR + r0 + 2 * p] = pw;
            }
        }

        // V(t) ready (newest pending group: K(t+1)); also publishes P^T
        asm volatile("cp.async.wait_group 1;\n");
        __syncthreads();

        // --- O += P V : row-pair-packed f32x2 ---
#pragma unroll 2
        for (int c = 0; c < KV_TILE; c++) {
            ulonglong2 pA = *(const ulonglong2*)&Ps[c * PSTR + r0];       // pairs 0,1
            ulonglong2 pB = *(const ulonglong2*)&Ps[c * PSTR + r0 + 4];   // pairs 2,3
            float4 v4 = *(const float4*)&Vs[c * KSTR + c0];
            u64 vx = splat2(v4.x), vy = splat2(v4.y);
            u64 vz = splat2(v4.z), vw = splat2(v4.w);
            O2[0][0] = f2fma(pA.x, vx, O2[0][0]);
            O2[0][1] = f2fma(pA.x, vy, O2[0][1]);
            O2[0][2] = f2fma(pA.x, vz, O2[0][2]);
            O2[0][3] = f2fma(pA.x, vw, O2[0][3]);
            O2[1][0] = f2fma(pA.y, vx, O2[1][0]);
            O2[1][1] = f2fma(pA.y, vy, O2[1][1]);
            O2[1][2] = f2fma(pA.y, vz, O2[1][2]);
            O2[1][3] = f2fma(pA.y, vw, O2[1][3]);
            O2[2][0] = f2fma(pB.x, vx, O2[2][0]);
            O2[2][1] = f2fma(pB.x, vy, O2[2][1]);
            O2[2][2] = f2fma(pB.x, vz, O2[2][2]);
            O2[2][3] = f2fma(pB.x, vw, O2[2][3]);
            O2[3][0] = f2fma(pB.y, vx, O2[3][0]);
            O2[3][1] = f2fma(pB.y, vy, O2[3][1]);
            O2[3][2] = f2fma(pB.y, vz, O2[3][2]);
            O2[3][3] = f2fma(pB.y, vw, O2[3][3]);
        }

        // all warps done reading Vs -> stream V(t+1)
        __syncthreads();
        issue_kv_tile(vb, cache_v, g_v, t + 1, h, tid);
    }

    // --- epilogue ---
#pragma unroll
    for (int p = 0; p < 4; p++) {
        int ra = q0 + r0 + 2 * p;
        int rb_ = ra + 1;
        if (ra < S_LEN) {
            float inv = 1.0f / l_[2 * p];
            float4 o = make_float4(f2lo(O2[p][0]) * inv, f2lo(O2[p][1]) * inv,
                                   f2lo(O2[p][2]) * inv, f2lo(O2[p][3]) * inv);
            *(float4*)(g_o + (size_t)ra * DIMN + h * HDN + c0) = o;
        }
        if (rb_ < S_LEN) {
            float inv = 1.0f / l_[2 * p + 1];
            float4 o = make_float4(f2hi(O2[p][0]) * inv, f2hi(O2[p][1]) * inv,
                                   f2hi(O2[p][2]) * inv, f2hi(O2[p][3]) * inv);
            *(float4*)(g_o + (size_t)rb_ * DIMN + h * HDN + c0) = o;
        }
    }
}

// =======================================================================
extern "C" void kernel_launch(void* const* d_in, const int* in_sizes, int n_in,
                              void* d_out, int out_size)
{
    (void)in_sizes; (void)n_in; (void)out_size;
    const float* x  = (const float*)d_in[0];
    const float* wq = (const float*)d_in[1];
    const float* bq = (const float*)d_in[2];
    const float* wk = (const float*)d_in[3];
    const float* bk = (const float*)d_in[4];
    const float* wv = (const float*)d_in[5];
    const float* bv = (const float*)d_in[6];
    const float* wo = (const float*)d_in[7];
    const float* bo = (const float*)d_in[8];
    const float* gq = (const float*)d_in[9];
    const float* gk = (const float*)d_in[10];
    const float* fc = (const float*)d_in[11];
    const float* fs = (const float*)d_in[12];
    const float* ck = (const float*)d_in[13];
    const float* cv = (const float*)d_in[14];
    float* out = (float*)d_out;

    cudaFuncSetAttribute(attn_kernel,
                         cudaFuncAttributeMaxDynamicSharedMemorySize, ATTN_SMEM);

    gemm_qkv<<<dim3(24, 13, 3), 256>>>(x, wq, bq, wk, bk, wv, bv);
    normrope_kernel<<<S_LEN, 256>>>(gq, gk, fc, fs);
    attn_kernel<<<dim3(25, NHN), 256, ATTN_SMEM>>>(ck, cv);
    gemm_out<<<dim3(24, 13), 256>>>(wo, bo, out);
}

// round 16
// speedup vs baseline: 2.0556x; 1.2439x over previous
#include <cuda_runtime.h>
#include <cstdint>

#define S_LEN   1560
#define DIMN    1536
#define NHN     12
#define HDN     128
#define LKV     10920
#define CSTART  9360
#define QK_SCALE 0.08838834764831845f

#define KV_TILE 64
#define NT_TILES ((LKV + KV_TILE - 1) / KV_TILE)   // 171

typedef unsigned long long u64;

// ---------------- scratch (device globals; no allocations) ----------------
__device__ float g_q[S_LEN * DIMN];
__device__ float g_k[S_LEN * DIMN];
__device__ float g_v[S_LEN * DIMN];
__device__ float g_o[S_LEN * DIMN];

// ---------------- packed f32x2 helpers ----------------
__device__ __forceinline__ u64 f2fma(u64 a, u64 b, u64 c) {
    u64 d;
    asm("fma.rn.f32x2 %0, %1, %2, %3;" : "=l"(d) : "l"(a), "l"(b), "l"(c));
    return d;
}
__device__ __forceinline__ u64 f2mul(u64 a, u64 b) {
    u64 d;
    asm("mul.rn.f32x2 %0, %1, %2;" : "=l"(d) : "l"(a), "l"(b));
    return d;
}
__device__ __forceinline__ u64 splat2(float x) {
    u64 d; unsigned xi = __float_as_uint(x);
    asm("mov.b64 %0, {%1, %1};" : "=l"(d) : "r"(xi));
    return d;
}
__device__ __forceinline__ u64 pack2(float lo, float hi) {
    u64 d;
    asm("mov.b64 %0, {%1, %2};" : "=l"(d) : "r"(__float_as_uint(lo)), "r"(__float_as_uint(hi)));
    return d;
}
__device__ __forceinline__ float f2lo(u64 v) { return __uint_as_float((unsigned)(v & 0xffffffffull)); }
__device__ __forceinline__ float f2hi(u64 v) { return __uint_as_float((unsigned)(v >> 32)); }

__device__ __forceinline__ void cp16(uint32_t dst, const float* src) {
    asm volatile("cp.async.cg.shared.global [%0], [%1], 16;\n"
                 :: "r"(dst), "l"(__cvta_generic_to_global((const void*)src)));
}

// =======================================================================
// NT GEMM: C[m][n] = sum_k A[m][k]*W[n][k] + bias[n]
// 128x64x16 tile, 256 threads, 8x4 microkernel, f2fma, reg prefetch.
// =======================================================================
__device__ __forceinline__ void gemm_body(const float* __restrict__ A,
                                          const float* __restrict__ W,
                                          const float* __restrict__ bias,
                                          float* __restrict__ C)
{
    __shared__ float As[16][128];
    __shared__ float Bs[16][64];

    const int m0 = blockIdx.y * 128;
    const int n0 = blockIdx.x * 64;
    const int tid = threadIdx.x;
    const int ty = tid >> 4, tx = tid & 15;
    const int lrA = tid >> 2;
    const int lkA = (tid & 3) * 4;

    u64 c2[8][2];
#pragma unroll
    for (int i = 0; i < 8; i++) { c2[i][0] = 0ull; c2[i][1] = 0ull; }

    float4 ra[2], rb;
#pragma unroll
    for (int q = 0; q < 2; q++) {
        int m = m0 + lrA + q * 64;
        ra[q] = (m < S_LEN) ? *(const float4*)(A + (size_t)m * DIMN + lkA)
                            : make_float4(0.f, 0.f, 0.f, 0.f);
    }
    rb = *(const float4*)(W + (size_t)(n0 + lrA) * DIMN + lkA);

    const int KT = DIMN / 16;
    for (int kt = 0; kt < KT; kt++) {
#pragma unroll
        for (int q = 0; q < 2; q++) {
            As[lkA + 0][lrA + q * 64] = ra[q].x;
            As[lkA + 1][lrA + q * 64] = ra[q].y;
            As[lkA + 2][lrA + q * 64] = ra[q].z;
            As[lkA + 3][lrA + q * 64] = ra[q].w;
        }
        Bs[lkA + 0][lrA] = rb.x;
        Bs[lkA + 1][lrA] = rb.y;
        Bs[lkA + 2][lrA] = rb.z;
        Bs[lkA + 3][lrA] = rb.w;
        __syncthreads();
        if (kt + 1 < KT) {
            int kb = (kt + 1) * 16 + lkA;
#pragma unroll
            for (int q = 0; q < 2; q++) {
                int m = m0 + lrA + q * 64;
                ra[q] = (m < S_LEN) ? *(const float4*)(A + (size_t)m * DIMN + kb)
                                    : make_float4(0.f, 0.f, 0.f, 0.f);
            }
            rb = *(const float4*)(W + (size_t)(n0 + lrA) * DIMN + kb);
        }
#pragma unroll
        for (int kk = 0; kk < 16; kk++) {
            float a[8];
            *(float4*)&a[0] = *(const float4*)&As[kk][ty * 8];
            *(float4*)&a[4] = *(const float4*)&As[kk][ty * 8 + 4];
            ulonglong2 b2 = *(const ulonglong2*)&Bs[kk][tx * 4];
#pragma unroll
            for (int i = 0; i < 8; i++) {
                u64 ai = splat2(a[i]);
                c2[i][0] = f2fma(ai, b2.x, c2[i][0]);
                c2[i][1] = f2fma(ai, b2.y, c2[i][1]);
            }
        }
        __syncthreads();
    }

    float4 bi = *(const float4*)(bias + n0 + tx * 4);
#pragma unroll
    for (int i = 0; i < 8; i++) {
        int m = m0 + ty * 8 + i;
        if (m >= S_LEN) continue;
        float4 r = make_float4(f2lo(c2[i][0]) + bi.x, f2hi(c2[i][0]) + bi.y,
                               f2lo(c2[i][1]) + bi.z, f2hi(c2[i][1]) + bi.w);
        *(float4*)(C + (size_t)m * DIMN + n0 + tx * 4) = r;
    }
}

__global__ void __launch_bounds__(256, 2) gemm_qkv(
    const float* __restrict__ x,
    const float* __restrict__ wq, const float* __restrict__ bq,
    const float* __restrict__ wk, const float* __restrict__ bk,
    const float* __restrict__ wv, const float* __restrict__ bv)
{
    const float* W; const float* B; float* C;
    if (blockIdx.z == 0)      { W = wq; B = bq; C = g_q; }
    else if (blockIdx.z == 1) { W = wk; B = bk; C = g_k; }
    else                      { W = wv; B = bv; C = g_v; }
    gemm_body(x, W, B, C);
}

__global__ void __launch_bounds__(256, 2) gemm_out(
    const float* __restrict__ wo, const float* __restrict__ bo,
    float* __restrict__ out)
{
    gemm_body(g_o, wo, bo, out);
}

// =======================================================================
// rmsnorm(1536) + 3-band RoPE, one block per token, in-place on g_q/g_k.
// =======================================================================
__global__ void __launch_bounds__(256) normrope_kernel(
    const float* __restrict__ gq, const float* __restrict__ gk,
    const float* __restrict__ fcos, const float* __restrict__ fsin)
{
    const int s = blockIdx.x;
    float* qr = g_q + (size_t)s * DIMN;
    float* kr = g_k + (size_t)s * DIMN;
    const int tid = threadIdx.x;

    float sq = 0.f, sk = 0.f;
#pragma unroll
    for (int u = 0; u < 6; u++) {
        float a = qr[tid + u * 256]; sq = fmaf(a, a, sq);
        float b = kr[tid + u * 256]; sk = fmaf(b, b, sk);
    }
#pragma unroll
    for (int off = 16; off; off >>= 1) {
        sq += __shfl_xor_sync(0xffffffffu, sq, off);
        sk += __shfl_xor_sync(0xffffffffu, sk, off);
    }
    __shared__ float red[2][8];
    if ((tid & 31) == 0) { red[0][tid >> 5] = sq; red[1][tid >> 5] = sk; }
    __syncthreads();
    float tq = 0.f, tk = 0.f;
#pragma unroll
    for (int w = 0; w < 8; w++) { tq += red[0][w]; tk += red[1][w]; }
    const float invq = rsqrtf(tq * (1.0f / DIMN) + 1e-6f);
    const float invk = rsqrtf(tk * (1.0f / DIMN) + 1e-6f);

    const int h_tok = s / 52;
    const int w_tok = s - h_tok * 52;

#pragma unroll
    for (int p = tid; p < NHN * 64; p += 256) {
        int hh = p >> 6;
        int c = p & 63;
        int r = (c < 22) ? 6 : ((c < 43) ? h_tok : w_tok);
        float cs = fcos[r * 64 + c];
        float sn = fsin[r * 64 + c];
        int idx = hh * HDN + 2 * c;

        float qe = qr[idx] * invq * gq[idx];
        float qo = qr[idx + 1] * invq * gq[idx + 1];
        qr[idx]     = qe * cs - qo * sn;
        qr[idx + 1] = qe * sn + qo * cs;

        float ke = kr[idx] * invk * gk[idx];
        float ko = kr[idx + 1] * invk * gk[idx + 1];
        kr[idx]     = ke * cs - ko * sn;
        kr[idx + 1] = ke * sn + ko * cs;
    }
}

// =======================================================================
// Flash attention v4: 64 q-rows x 64 kv per tile, 256 threads (8 warps).
// Warp w owns q-rows w*8..w*8+7; lane owns kv cols {lane, lane+32}.
// K stored swizzled (chunk ^ (row&7), stride 128) -> conflict-free reads.
// P^T stored as u64 row-pairs, rows padded to 33 u64 -> conflict-free STS.
// smem: Q 32KB + K 32KB + V 32KB + P 16.5KB = 115200 B -> 2 CTAs/SM.
// =======================================================================
#define ATTN_SMEM (3 * 64 * 128 * 4 + 64 * 33 * 8)   // 115200

__device__ __forceinline__ void issue_k_tile(uint32_t base,
                                             const float* __restrict__ cache,
                                             const float* __restrict__ gnew,
                                             int t, int h, int tid)
{
    if (t < NT_TILES) {
        const int kv0 = t * KV_TILE;
#pragma unroll
        for (int jj = 0; jj < 8; jj++) {
            int ch = jj * 256 + tid;           // 0..2047
            int row = ch >> 5;                 // 0..63
            int cc = ch & 31;                  // chunk col 0..31
            int pos = kv0 + row;
            if (pos > LKV - 1) pos = LKV - 1;
            const float* src = (pos < CSTART)
                ? cache + ((size_t)pos * NHN + h) * HDN + cc * 4
                : gnew + (size_t)(pos - CSTART) * DIMN + h * HDN + cc * 4;
            int sw = cc ^ (row & 7);           // XOR swizzle
            cp16(base + (unsigned)(row * 128 + sw * 4) * 4u, src);
        }
    }
    asm volatile("cp.async.commit_group;\n");
}

__device__ __forceinline__ void issue_v_tile(uint32_t base,
                                             const float* __restrict__ cache,
                                             const float* __restrict__ gnew,
                                             int t, int h, int tid)
{
    if (t < NT_TILES) {
        const int kv0 = t * KV_TILE;
#pragma unroll
        for (int jj = 0; jj < 8; jj++) {
            int ch = jj * 256 + tid;
            int row = ch >> 5;
            int cc = ch & 31;
            int pos = kv0 + row;
            if (pos > LKV - 1) pos = LKV - 1;
            const float* src = (pos < CSTART)
                ? cache + ((size_t)pos * NHN + h) * HDN + cc * 4
                : gnew + (size_t)(pos - CSTART) * DIMN + h * HDN + cc * 4;
            cp16(base + (unsigned)(row * 128 + cc * 4) * 4u, src);
        }
    }
    asm volatile("cp.async.commit_group;\n");
}

__global__ void __launch_bounds__(256, 2) attn_kernel(
    const float* __restrict__ cache_k, const float* __restrict__ cache_v)
{
    extern __shared__ __align__(16) float sm[];
    float* Qs = sm;                      // 64 x 128
    float* Ks = Qs + 64 * 128;           // 64 x 128 (swizzled)
    float* Vs = Ks + 64 * 128;           // 64 x 128 (linear)
    u64*   Pu = (u64*)(Vs + 64 * 128);   // 64 kv x 33 u64 (row-pair packed)

    const int h  = blockIdx.y;
    const int q0 = blockIdx.x * 64;
    const int tid = threadIdx.x;
    const int w = tid >> 5;
    const int lane = tid & 31;
    const int r0 = w * 8;                // q-row base for this warp
    const int w4 = w * 4;                // row-pair base
    const int d0 = lane * 4;             // PV d-column base
    const int xr = lane & 7;             // K swizzle key (same for lane and lane+32)

    const float* Kb0 = Ks + lane * 128;
    const float* Kb1 = Ks + (lane + 32) * 128;

    const uint32_t kb = (uint32_t)__cvta_generic_to_shared(Ks);
    const uint32_t vb = (uint32_t)__cvta_generic_to_shared(Vs);

    // --- load Q tile (pre-scaled) ---
#pragma unroll
    for (int jj = 0; jj < 8; jj++) {
        int ch = jj * 256 + tid;
        int row = ch >> 5;
        int cc = (ch & 31) * 4;
        int r = q0 + row;
        float4 v = (r < S_LEN)
            ? *(const float4*)(g_q + (size_t)r * DIMN + h * HDN + cc)
            : make_float4(0.f, 0.f, 0.f, 0.f);
        v.x *= QK_SCALE; v.y *= QK_SCALE; v.z *= QK_SCALE; v.w *= QK_SCALE;
        *(float4*)&Qs[row * 128 + cc] = v;
    }

    float m_[8], l_[8];
    u64 O2[4][4];
#pragma unroll
    for (int i = 0; i < 8; i++) { m_[i] = -1e30f; l_[i] = 0.f; }
#pragma unroll
    for (int p = 0; p < 4; p++)
#pragma unroll
        for (int d = 0; d < 4; d++) O2[p][d] = 0ull;

    issue_k_tile(kb, cache_k, g_k, 0, h, tid);
    issue_v_tile(vb, cache_v, g_v, 0, h, tid);

    for (int t = 0; t < NT_TILES; t++) {
        asm volatile("cp.async.wait_group 1;\n");   // K(t) done (V(t) pending)
        __syncthreads();

        // --- S = Q K^T : 8 rows x 2 cols per thread, f32x2 over k ---
        u64 s2[8][2];
#pragma unroll
        for (int i = 0; i < 8; i++) { s2[i][0] = 0ull; s2[i][1] = 0ull; }

#pragma unroll 4
        for (int kc = 0; kc < 32; kc++) {
            int sw = ((kc ^ xr) << 2);
            ulonglong2 b0 = *(const ulonglong2*)(Kb0 + sw);
            ulonglong2 b1 = *(const ulonglong2*)(Kb1 + sw);
            int k = kc << 2;
#pragma unroll
            for (int i = 0; i < 8; i++) {
                ulonglong2 a = *(const ulonglong2*)&Qs[(r0 + i) * 128 + k];
                s2[i][0] = f2fma(a.x, b0.x, s2[i][0]);
                s2[i][0] = f2fma(a.y, b0.y, s2[i][0]);
                s2[i][1] = f2fma(a.x, b1.x, s2[i][1]);
                s2[i][1] = f2fma(a.y, b1.y, s2[i][1]);
            }
        }

        float s_[8][2];
#pragma unroll
        for (int i = 0; i < 8; i++) {
            s_[i][0] = f2lo(s2[i][0]) + f2hi(s2[i][0]);
            s_[i][1] = f2lo(s2[i][1]) + f2hi(s2[i][1]);
        }

        if (t == NT_TILES - 1) {
            const int kv0 = t * KV_TILE;
            if (kv0 + lane >= LKV)
#pragma unroll
                for (int i = 0; i < 8; i++) s_[i][0] = -1e30f;
            if (kv0 + lane + 32 >= LKV)
#pragma unroll
                for (int i = 0; i < 8; i++) s_[i][1] = -1e30f;
        }

        __syncthreads();                           // all warps done reading K
        issue_k_tile(kb, cache_k, g_k, t + 1, h, tid);

        // --- online softmax ---
        float al[8];
#pragma unroll
        for (int i = 0; i < 8; i++) {
            float mt = fmaxf(s_[i][0], s_[i][1]);
#pragma unroll
            for (int off = 16; off; off >>= 1)
                mt = fmaxf(mt, __shfl_xor_sync(0xffffffffu, mt, off));
            float mn = fmaxf(m_[i], mt);
            al[i] = __expf(m_[i] - mn);
            m_[i] = mn;
            float p0 = __expf(s_[i][0] - mn);
            float p1 = __expf(s_[i][1] - mn);
            s_[i][0] = p0; s_[i][1] = p1;
            float rs = p0 + p1;
#pragma unroll
            for (int off = 16; off; off >>= 1)
                rs += __shfl_xor_sync(0xffffffffu, rs, off);
            l_[i] = l_[i] * al[i] + rs;
        }
#pragma unroll
        for (int p = 0; p < 4; p++) {
            u64 a2 = pack2(al[2 * p], al[2 * p + 1]);
#pragma unroll
            for (int d = 0; d < 4; d++) O2[p][d] = f2mul(O2[p][d], a2);
        }

        // --- write P^T (row-pair packed); each warp reads only its own pairs ---
#pragma unroll
        for (int j = 0; j < 2; j++) {
            int col = lane + 32 * j;
#pragma unroll
            for (int p = 0; p < 4; p++)
                Pu[col * 33 + w4 + p] = pack2(s_[2 * p][j], s_[2 * p + 1][j]);
        }
        __syncwarp();

        asm volatile("cp.async.wait_group 1;\n");   // V(t) done (K(t+1) pending)
        __syncthreads();

        // --- O += P V ---
#pragma unroll 2
        for (int c = 0; c < KV_TILE; c++) {
            u64 pa0 = Pu[c * 33 + w4 + 0];
            u64 pa1 = Pu[c * 33 + w4 + 1];
            u64 pa2 = Pu[c * 33 + w4 + 2];
            u64 pa3 = Pu[c * 33 + w4 + 3];
            float4 v = *(const float4*)&Vs[c * 128 + d0];
            u64 vx = splat2(v.x), vy = splat2(v.y);
            u64 vz = splat2(v.z), vw = splat2(v.w);
            O2[0][0] = f2fma(pa0, vx, O2[0][0]);
            O2[0][1] = f2fma(pa0, vy, O2[0][1]);
            O2[0][2] = f2fma(pa0, vz, O2[0][2]);
            O2[0][3] = f2fma(pa0, vw, O2[0][3]);
            O2[1][0] = f2fma(pa1, vx, O2[1][0]);
            O2[1][1] = f2fma(pa1, vy, O2[1][1]);
            O2[1][2] = f2fma(pa1, vz, O2[1][2]);
            O2[1][3] = f2fma(pa1, vw, O2[1][3]);
            O2[2][0] = f2fma(pa2, vx, O2[2][0]);
            O2[2][1] = f2fma(pa2, vy, O2[2][1]);
            O2[2][2] = f2fma(pa2, vz, O2[2][2]);
            O2[2][3] = f2fma(pa2, vw, O2[2][3]);
            O2[3][0] = f2fma(pa3, vx, O2[3][0]);
            O2[3][1] = f2fma(pa3, vy, O2[3][1]);
            O2[3][2] = f2fma(pa3, vz, O2[3][2]);
            O2[3][3] = f2fma(pa3, vw, O2[3][3]);
        }

        __syncthreads();                           // all warps done reading V
        issue_v_tile(vb, cache_v, g_v, t + 1, h, tid);
    }

    // --- epilogue ---
#pragma unroll
    for (int p = 0; p < 4; p++) {
        int ra = q0 + r0 + 2 * p;
        int rb_ = ra + 1;
        if (ra < S_LEN) {
            float inv = 1.0f / l_[2 * p];
            float4 o = make_float4(f2lo(O2[p][0]) * inv, f2lo(O2[p][1]) * inv,
                                   f2lo(O2[p][2]) * inv, f2lo(O2[p][3]) * inv);
            *(float4*)(g_o + (size_t)ra * DIMN + h * HDN + d0) = o;
        }
        if (rb_ < S_LEN) {
            float inv = 1.0f / l_[2 * p + 1];
            float4 o = make_float4(f2hi(O2[p][0]) * inv, f2hi(O2[p][1]) * inv,
                                   f2hi(O2[p][2]) * inv, f2hi(O2[p][3]) * inv);
            *(float4*)(g_o + (size_t)rb_ * DIMN + h * HDN + d0) = o;
        }
    }
}

// =======================================================================
extern "C" void kernel_launch(void* const* d_in, const int* in_sizes, int n_in,
                              void* d_out, int out_size)
{
    (void)in_sizes; (void)n_in; (void)out_size;
    const float* x  = (const float*)d_in[0];
    const float* wq = (const float*)d_in[1];
    const float* bq = (const float*)d_in[2];
    const float* wk = (const float*)d_in[3];
    const float* bk = (const float*)d_in[4];
    const float* wv = (const float*)d_in[5];
    const float* bv = (const float*)d_in[6];
    const float* wo = (const float*)d_in[7];
    const float* bo = (const float*)d_in[8];
    const float* gq = (const float*)d_in[9];
    const float* gk = (const float*)d_in[10];
    const float* fc = (const float*)d_in[11];
    const float* fs = (const float*)d_in[12];
    const float* ck = (const float*)d_in[13];
    const float* cv = (const float*)d_in[14];
    float* out = (float*)d_out;

    cudaFuncSetAttribute(attn_kernel,
                         cudaFuncAttributeMaxDynamicSharedMemorySize, ATTN_SMEM);

    gemm_qkv<<<dim3(24, 13, 3), 256>>>(x, wq, bq, wk, bk, wv, bv);
    normrope_kernel<<<S_LEN, 256>>>(gq, gk, fc, fs);
    attn_kernel<<<dim3(25, NHN), 256, ATTN_SMEM>>>(ck, cv);
    gemm_out<<<dim3(24, 13), 256>>>(wo, bo, out);
}

// round 17
// speedup vs baseline: 2.1170x; 1.0298x over previous
#include <cuda_runtime.h>
#include <cstdint>

#define S_LEN   1560
#define DIMN    1536
#define NHN     12
#define HDN     128
#define LKV     10920
#define CSTART  9360
#define QK_SCALE 0.08838834764831845f

#define KV_TILE 64
#define NT_TILES ((LKV + KV_TILE - 1) / KV_TILE)   // 171

typedef unsigned long long u64;

// ---------------- scratch (device globals; no allocations) ----------------
__device__ float g_q[S_LEN * DIMN];
__device__ float g_k[S_LEN * DIMN];
__device__ float g_v[S_LEN * DIMN];
__device__ float g_o[S_LEN * DIMN];

// ---------------- packed f32x2 helpers ----------------
__device__ __forceinline__ u64 f2fma(u64 a, u64 b, u64 c) {
    u64 d;
    asm("fma.rn.f32x2 %0, %1, %2, %3;" : "=l"(d) : "l"(a), "l"(b), "l"(c));
    return d;
}
__device__ __forceinline__ u64 f2mul(u64 a, u64 b) {
    u64 d;
    asm("mul.rn.f32x2 %0, %1, %2;" : "=l"(d) : "l"(a), "l"(b));
    return d;
}
__device__ __forceinline__ u64 splat2(float x) {
    u64 d; unsigned xi = __float_as_uint(x);
    asm("mov.b64 %0, {%1, %1};" : "=l"(d) : "r"(xi));
    return d;
}
__device__ __forceinline__ u64 pack2(float lo, float hi) {
    u64 d;
    asm("mov.b64 %0, {%1, %2};" : "=l"(d) : "r"(__float_as_uint(lo)), "r"(__float_as_uint(hi)));
    return d;
}
__device__ __forceinline__ float f2lo(u64 v) { return __uint_as_float((unsigned)(v & 0xffffffffull)); }
__device__ __forceinline__ float f2hi(u64 v) { return __uint_as_float((unsigned)(v >> 32)); }

__device__ __forceinline__ void cp16(uint32_t dst, const float* src) {
    asm volatile("cp.async.cg.shared.global [%0], [%1], 16;\n"
                 :: "r"(dst), "l"(__cvta_generic_to_global((const void*)src)));
}

// =======================================================================
// NT GEMM v2: C[m][n] = sum_k A[m][k]*W[n][k] + bias[n]
// 128x128x16 tile, 256 threads, 8x8 split-quad microkernel (f2fma,
// n-pair packed). Smem rows padded to 132 -> conflict-free frag loads.
// =======================================================================
__device__ __forceinline__ void gemm_body(const float* __restrict__ A,
                                          const float* __restrict__ W,
                                          const float* __restrict__ bias,
                                          float* __restrict__ C)
{
    __shared__ float As[16][132];
    __shared__ float Bs[16][132];

    const int m0 = blockIdx.y * 128;
    const int n0 = blockIdx.x * 128;
    const int tid = threadIdx.x;
    const int ty = tid >> 4, tx = tid & 15;
    const int lr = tid >> 2;            // 0..63
    const int lk = (tid & 3) * 4;       // 0,4,8,12

    u64 c2[8][4];
#pragma unroll
    for (int i = 0; i < 8; i++)
#pragma unroll
        for (int j = 0; j < 4; j++) c2[i][j] = 0ull;

    float4 ra[2], rb[2];
#pragma unroll
    for (int q = 0; q < 2; q++) {
        int m = m0 + lr + q * 64;
        ra[q] = (m < S_LEN) ? *(const float4*)(A + (size_t)m * DIMN + lk)
                            : make_float4(0.f, 0.f, 0.f, 0.f);
        rb[q] = *(const float4*)(W + (size_t)(n0 + lr + q * 64) * DIMN + lk);
    }

    const int KT = DIMN / 16;  // 96
    for (int kt = 0; kt < KT; kt++) {
#pragma unroll
        for (int q = 0; q < 2; q++) {
            As[lk + 0][lr + q * 64] = ra[q].x;
            As[lk + 1][lr + q * 64] = ra[q].y;
            As[lk + 2][lr + q * 64] = ra[q].z;
            As[lk + 3][lr + q * 64] = ra[q].w;
            Bs[lk + 0][lr + q * 64] = rb[q].x;
            Bs[lk + 1][lr + q * 64] = rb[q].y;
            Bs[lk + 2][lr + q * 64] = rb[q].z;
            Bs[lk + 3][lr + q * 64] = rb[q].w;
        }
        __syncthreads();
        if (kt + 1 < KT) {
            int kb = (kt + 1) * 16 + lk;
#pragma unroll
            for (int q = 0; q < 2; q++) {
                int m = m0 + lr + q * 64;
                ra[q] = (m < S_LEN) ? *(const float4*)(A + (size_t)m * DIMN + kb)
                                    : make_float4(0.f, 0.f, 0.f, 0.f);
                rb[q] = *(const float4*)(W + (size_t)(n0 + lr + q * 64) * DIMN + kb);
            }
        }
#pragma unroll
        for (int kk = 0; kk < 16; kk++) {
            float4 a0 = *(const float4*)&As[kk][ty * 4];
            float4 a1 = *(const float4*)&As[kk][ty * 4 + 64];
            ulonglong2 b0 = *(const ulonglong2*)&Bs[kk][tx * 4];
            ulonglong2 b1 = *(const ulonglong2*)&Bs[kk][tx * 4 + 64];
            float alo[8] = {a0.x, a0.y, a0.z, a0.w, a1.x, a1.y, a1.z, a1.w};
#pragma unroll
            for (int i = 0; i < 8; i++) {
                u64 ai = splat2(alo[i]);
                c2[i][0] = f2fma(ai, b0.x, c2[i][0]);
                c2[i][1] = f2fma(ai, b0.y, c2[i][1]);
                c2[i][2] = f2fma(ai, b1.x, c2[i][2]);
                c2[i][3] = f2fma(ai, b1.y, c2[i][3]);
            }
        }
        __syncthreads();
    }

    float4 bi0 = *(const float4*)(bias + n0 + tx * 4);
    float4 bi1 = *(const float4*)(bias + n0 + 64 + tx * 4);
#pragma unroll
    for (int i = 0; i < 8; i++) {
        int m = m0 + ty * 4 + (i >> 2) * 64 + (i & 3);
        if (m >= S_LEN) continue;
        float4 r0 = make_float4(f2lo(c2[i][0]) + bi0.x, f2hi(c2[i][0]) + bi0.y,
                                f2lo(c2[i][1]) + bi0.z, f2hi(c2[i][1]) + bi0.w);
        float4 r1 = make_float4(f2lo(c2[i][2]) + bi1.x, f2hi(c2[i][2]) + bi1.y,
                                f2lo(c2[i][3]) + bi1.z, f2hi(c2[i][3]) + bi1.w);
        *(float4*)(C + (size_t)m * DIMN + n0 + tx * 4) = r0;
        *(float4*)(C + (size_t)m * DIMN + n0 + 64 + tx * 4) = r1;
    }
}

__global__ void __launch_bounds__(256, 2) gemm_qkv(
    const float* __restrict__ x,
    const float* __restrict__ wq, const float* __restrict__ bq,
    const float* __restrict__ wk, const float* __restrict__ bk,
    const float* __restrict__ wv, const float* __restrict__ bv)
{
    const float* W; const float* B; float* C;
    if (blockIdx.z == 0)      { W = wq; B = bq; C = g_q; }
    else if (blockIdx.z == 1) { W = wk; B = bk; C = g_k; }
    else                      { W = wv; B = bv; C = g_v; }
    gemm_body(x, W, B, C);
}

__global__ void __launch_bounds__(256, 2) gemm_out(
    const float* __restrict__ wo, const float* __restrict__ bo,
    float* __restrict__ out)
{
    gemm_body(g_o, wo, bo, out);
}

// =======================================================================
// rmsnorm(1536) + 3-band RoPE, one block per token, in-place on g_q/g_k.
// =======================================================================
__global__ void __launch_bounds__(256) normrope_kernel(
    const float* __restrict__ gq, const float* __restrict__ gk,
    const float* __restrict__ fcos, const float* __restrict__ fsin)
{
    const int s = blockIdx.x;
    float* qr = g_q + (size_t)s * DIMN;
    float* kr = g_k + (size_t)s * DIMN;
    const int tid = threadIdx.x;

    float sq = 0.f, sk = 0.f;
#pragma unroll
    for (int u = 0; u < 6; u++) {
        float a = qr[tid + u * 256]; sq = fmaf(a, a, sq);
        float b = kr[tid + u * 256]; sk = fmaf(b, b, sk);
    }
#pragma unroll
    for (int off = 16; off; off >>= 1) {
        sq += __shfl_xor_sync(0xffffffffu, sq, off);
        sk += __shfl_xor_sync(0xffffffffu, sk, off);
    }
    __shared__ float red[2][8];
    if ((tid & 31) == 0) { red[0][tid >> 5] = sq; red[1][tid >> 5] = sk; }
    __syncthreads();
    float tq = 0.f, tk = 0.f;
#pragma unroll
    for (int w = 0; w < 8; w++) { tq += red[0][w]; tk += red[1][w]; }
    const float invq = rsqrtf(tq * (1.0f / DIMN) + 1e-6f);
    const float invk = rsqrtf(tk * (1.0f / DIMN) + 1e-6f);

    const int h_tok = s / 52;
    const int w_tok = s - h_tok * 52;

#pragma unroll
    for (int p = tid; p < NHN * 64; p += 256) {
        int hh = p >> 6;
        int c = p & 63;
        int r = (c < 22) ? 6 : ((c < 43) ? h_tok : w_tok);
        float cs = fcos[r * 64 + c];
        float sn = fsin[r * 64 + c];
        int idx = hh * HDN + 2 * c;

        float qe = qr[idx] * invq * gq[idx];
        float qo = qr[idx + 1] * invq * gq[idx + 1];
        qr[idx]     = qe * cs - qo * sn;
        qr[idx + 1] = qe * sn + qo * cs;

        float ke = kr[idx] * invk * gk[idx];
        float ko = kr[idx + 1] * invk * gk[idx + 1];
        kr[idx]     = ke * cs - ko * sn;
        kr[idx + 1] = ke * sn + ko * cs;
    }
}

// =======================================================================
// Flash attention v4 (unchanged from R16): 64x64 tiles, 256 threads.
// =======================================================================
#define ATTN_SMEM (3 * 64 * 128 * 4 + 64 * 33 * 8)   // 115200

__device__ __forceinline__ void issue_k_tile(uint32_t base,
                                             const float* __restrict__ cache,
                                             const float* __restrict__ gnew,
                                             int t, int h, int tid)
{
    if (t < NT_TILES) {
        const int kv0 = t * KV_TILE;
#pragma unroll
        for (int jj = 0; jj < 8; jj++) {
            int ch = jj * 256 + tid;
            int row = ch >> 5;
            int cc = ch & 31;
            int pos = kv0 + row;
            if (pos > LKV - 1) pos = LKV - 1;
            const float* src = (pos < CSTART)
                ? cache + ((size_t)pos * NHN + h) * HDN + cc * 4
                : gnew + (size_t)(pos - CSTART) * DIMN + h * HDN + cc * 4;
            int sw = cc ^ (row & 7);
            cp16(base + (unsigned)(row * 128 + sw * 4) * 4u, src);
        }
    }
    asm volatile("cp.async.commit_group;\n");
}

__device__ __forceinline__ void issue_v_tile(uint32_t base,
                                             const float* __restrict__ cache,
                                             const float* __restrict__ gnew,
                                             int t, int h, int tid)
{
    if (t < NT_TILES) {
        const int kv0 = t * KV_TILE;
#pragma unroll
        for (int jj = 0; jj < 8; jj++) {
            int ch = jj * 256 + tid;
            int row = ch >> 5;
            int cc = ch & 31;
            int pos = kv0 + row;
            if (pos > LKV - 1) pos = LKV - 1;
            const float* src = (pos < CSTART)
                ? cache + ((size_t)pos * NHN + h) * HDN + cc * 4
                : gnew + (size_t)(pos - CSTART) * DIMN + h * HDN + cc * 4;
            cp16(base + (unsigned)(row * 128 + cc * 4) * 4u, src);
        }
    }
    asm volatile("cp.async.commit_group;\n");
}

__global__ void __launch_bounds__(256, 2) attn_kernel(
    const float* __restrict__ cache_k, const float* __restrict__ cache_v)
{
    extern __shared__ __align__(16) float sm[];
    float* Qs = sm;                      // 64 x 128
    float* Ks = Qs + 64 * 128;           // 64 x 128 (swizzled)
    float* Vs = Ks + 64 * 128;           // 64 x 128 (linear)
    u64*   Pu = (u64*)(Vs + 64 * 128);   // 64 kv x 33 u64

    const int h  = blockIdx.y;
    const int q0 = blockIdx.x * 64;
    const int tid = threadIdx.x;
    const int w = tid >> 5;
    const int lane = tid & 31;
    const int r0 = w * 8;
    const int w4 = w * 4;
    const int d0 = lane * 4;
    const int xr = lane & 7;

    const float* Kb0 = Ks + lane * 128;
    const float* Kb1 = Ks + (lane + 32) * 128;

    const uint32_t kb = (uint32_t)__cvta_generic_to_shared(Ks);
    const uint32_t vb = (uint32_t)__cvta_generic_to_shared(Vs);

#pragma unroll
    for (int jj = 0; jj < 8; jj++) {
        int ch = jj * 256 + tid;
        int row = ch >> 5;
        int cc = (ch & 31) * 4;
        int r = q0 + row;
        float4 v = (r < S_LEN)
            ? *(const float4*)(g_q + (size_t)r * DIMN + h * HDN + cc)
            : make_float4(0.f, 0.f, 0.f, 0.f);
        v.x *= QK_SCALE; v.y *= QK_SCALE; v.z *= QK_SCALE; v.w *= QK_SCALE;
        *(float4*)&Qs[row * 128 + cc] = v;
    }

    float m_[8], l_[8];
    u64 O2[4][4];
#pragma unroll
    for (int i = 0; i < 8; i++) { m_[i] = -1e30f; l_[i] = 0.f; }
#pragma unroll
    for (int p = 0; p < 4; p++)
#pragma unroll
        for (int d = 0; d < 4; d++) O2[p][d] = 0ull;

    issue_k_tile(kb, cache_k, g_k, 0, h, tid);
    issue_v_tile(vb, cache_v, g_v, 0, h, tid);

    for (int t = 0; t < NT_TILES; t++) {
        asm volatile("cp.async.wait_group 1;\n");
        __syncthreads();

        u64 s2[8][2];
#pragma unroll
        for (int i = 0; i < 8; i++) { s2[i][0] = 0ull; s2[i][1] = 0ull; }

#pragma unroll 4
        for (int kc = 0; kc < 32; kc++) {
            int sw = ((kc ^ xr) << 2);
            ulonglong2 b0 = *(const ulonglong2*)(Kb0 + sw);
            ulonglong2 b1 = *(const ulonglong2*)(Kb1 + sw);
            int k = kc << 2;
#pragma unroll
            for (int i = 0; i < 8; i++) {
                ulonglong2 a = *(const ulonglong2*)&Qs[(r0 + i) * 128 + k];
                s2[i][0] = f2fma(a.x, b0.x, s2[i][0]);
                s2[i][0] = f2fma(a.y, b0.y, s2[i][0]);
                s2[i][1] = f2fma(a.x, b1.x, s2[i][1]);
                s2[i][1] = f2fma(a.y, b1.y, s2[i][1]);
            }
        }

        float s_[8][2];
#pragma unroll
        for (int i = 0; i < 8; i++) {
            s_[i][0] = f2lo(s2[i][0]) + f2hi(s2[i][0]);
            s_[i][1] = f2lo(s2[i][1]) + f2hi(s2[i][1]);
        }

        if (t == NT_TILES - 1) {
            const int kv0 = t * KV_TILE;
            if (kv0 + lane >= LKV)
#pragma unroll
                for (int i = 0; i < 8; i++) s_[i][0] = -1e30f;
            if (kv0 + lane + 32 >= LKV)
#pragma unroll
                for (int i = 0; i < 8; i++) s_[i][1] = -1e30f;
        }

        __syncthreads();
        issue_k_tile(kb, cache_k, g_k, t + 1, h, tid);

        float al[8];
#pragma unroll
        for (int i = 0; i < 8; i++) {
            float mt = fmaxf(s_[i][0], s_[i][1]);
#pragma unroll
            for (int off = 16; off; off >>= 1)
                mt = fmaxf(mt, __shfl_xor_sync(0xffffffffu, mt, off));
            float mn = fmaxf(m_[i], mt);
            al[i] = __expf(m_[i] - mn);
            m_[i] = mn;
            float p0 = __expf(s_[i][0] - mn);
            float p1 = __expf(s_[i][1] - mn);
            s_[i][0] = p0; s_[i][1] = p1;
            float rs = p0 + p1;
#pragma unroll
            for (int off = 16; off; off >>= 1)
                rs += __shfl_xor_sync(0xffffffffu, rs, off);
            l_[i] = l_[i] * al[i] + rs;
        }
#pragma unroll
        for (int p = 0; p < 4; p++) {
            u64 a2 = pack2(al[2 * p], al[2 * p + 1]);
#pragma unroll
            for (int d = 0; d < 4; d++) O2[p][d] = f2mul(O2[p][d], a2);
        }

#pragma unroll
        for (int j = 0; j < 2; j++) {
            int col = lane + 32 * j;
#pragma unroll
            for (int p = 0; p < 4; p++)
                Pu[col * 33 + w4 + p] = pack2(s_[2 * p][j], s_[2 * p + 1][j]);
        }
        __syncwarp();

        asm volatile("cp.async.wait_group 1;\n");
        __syncthreads();

#pragma unroll 2
        for (int c = 0; c < KV_TILE; c++) {
            u64 pa0 = Pu[c * 33 + w4 + 0];
            u64 pa1 = Pu[c * 33 + w4 + 1];
            u64 pa2 = Pu[c * 33 + w4 + 2];
            u64 pa3 = Pu[c * 33 + w4 + 3];
            float4 v = *(const float4*)&Vs[c * 128 + d0];
            u64 vx = splat2(v.x), vy = splat2(v.y);
            u64 vz = splat2(v.z), vw = splat2(v.w);
            O2[0][0] = f2fma(pa0, vx, O2[0][0]);
            O2[0][1] = f2fma(pa0, vy, O2[0][1]);
            O2[0][2] = f2fma(pa0, vz, O2[0][2]);
            O2[0][3] = f2fma(pa0, vw, O2[0][3]);
            O2[1][0] = f2fma(pa1, vx, O2[1][0]);
            O2[1][1] = f2fma(pa1, vy, O2[1][1]);
            O2[1][2] = f2fma(pa1, vz, O2[1][2]);
            O2[1][3] = f2fma(pa1, vw, O2[1][3]);
            O2[2][0] = f2fma(pa2, vx, O2[2][0]);
            O2[2][1] = f2fma(pa2, vy, O2[2][1]);
            O2[2][2] = f2fma(pa2, vz, O2[2][2]);
            O2[2][3] = f2fma(pa2, vw, O2[2][3]);
            O2[3][0] = f2fma(pa3, vx, O2[3][0]);
            O2[3][1] = f2fma(pa3, vy, O2[3][1]);
            O2[3][2] = f2fma(pa3, vz, O2[3][2]);
            O2[3][3] = f2fma(pa3, vw, O2[3][3]);
        }

        __syncthreads();
        issue_v_tile(vb, cache_v, g_v, t + 1, h, tid);
    }

#pragma unroll
    for (int p = 0; p < 4; p++) {
        int ra = q0 + r0 + 2 * p;
        int rb_ = ra + 1;
        if (ra < S_LEN) {
            float inv = 1.0f / l_[2 * p];
            float4 o = make_float4(f2lo(O2[p][0]) * inv, f2lo(O2[p][1]) * inv,
                                   f2lo(O2[p][2]) * inv, f2lo(O2[p][3]) * inv);
            *(float4*)(g_o + (size_t)ra * DIMN + h * HDN + d0) = o;
        }
        if (rb_ < S_LEN) {
            float inv = 1.0f / l_[2 * p + 1];
            float4 o = make_float4(f2hi(O2[p][0]) * inv, f2hi(O2[p][1]) * inv,
                                   f2hi(O2[p][2]) * inv, f2hi(O2[p][3]) * inv);
            *(float4*)(g_o + (size_t)rb_ * DIMN + h * HDN + d0) = o;
        }
    }
}

// =======================================================================
extern "C" void kernel_launch(void* const* d_in, const int* in_sizes, int n_in,
                              void* d_out, int out_size)
{
    (void)in_sizes; (void)n_in; (void)out_size;
    const float* x  = (const float*)d_in[0];
    const float* wq = (const float*)d_in[1];
    const float* bq = (const float*)d_in[2];
    const float* wk = (const float*)d_in[3];
    const float* bk = (const float*)d_in[4];
    const float* wv = (const float*)d_in[5];
    const float* bv = (const float*)d_in[6];
    const float* wo = (const float*)d_in[7];
    const float* bo = (const float*)d_in[8];
    const float* gq = (const float*)d_in[9];
    const float* gk = (const float*)d_in[10];
    const float* fc = (const float*)d_in[11];
    const float* fs = (const float*)d_in[12];
    const float* ck = (const float*)d_in[13];
    const float* cv = (const float*)d_in[14];
    float* out = (float*)d_out;

    cudaFuncSetAttribute(attn_kernel,
                         cudaFuncAttributeMaxDynamicSharedMemorySize, ATTN_SMEM);

    gemm_qkv<<<dim3(12, 13, 3), 256>>>(x, wq, bq, wk, bk, wv, bv);
    normrope_kernel<<<S_LEN, 256>>>(gq, gk, fc, fs);
    attn_kernel<<<dim3(25, NHN), 256, ATTN_SMEM>>>(ck, cv);
    gemm_out<<<dim3(12, 13), 256>>>(wo, bo, out);
}